// round 6
// baseline (speedup 1.0000x reference)
#include <cuda_runtime.h>
#include <cuda_bf16.h>
#include <math.h>
#include <stdint.h>

// ---------------------------------------------------------------------------
// Problem constants
// ---------------------------------------------------------------------------
#define BDIM   8192
#define DDIM   1024
#define HDIM   2048
#define H2DIM  1024
#define CDIM   1000
#define KDIM   128
#define EDIM   8
#define TOPK   2
#define MAXROWS (BDIM * TOPK)   // 16384 grouped rows

// ---------------------------------------------------------------------------
// Scratch (device globals — no allocation allowed)
// ---------------------------------------------------------------------------
__device__ float g_h    [(size_t)BDIM * HDIM];
__device__ float g_feats[(size_t)BDIM * HDIM];
__device__ float g_pk   [(size_t)BDIM * KDIM];
__device__ float g_keysn[EDIM * KDIM];
__device__ float g_sim  [BDIM * EDIM];
__device__ float g_weights[BDIM * EDIM];
__device__ float g_wslot[BDIM * TOPK];
__device__ int   g_topi [BDIM * TOPK];
__device__ int   g_counts[EDIM];
__device__ int   g_offsets[EDIM + 1];
__device__ int   g_cursor[EDIM];
__device__ int   g_list [MAXROWS];
__device__ int   g_pos  [BDIM * TOPK];
__device__ float g_h1   [(size_t)MAXROWS * HDIM];
__device__ float g_h2   [(size_t)MAXROWS * H2DIM];
__device__ float g_eout [(size_t)MAXROWS * CDIM];

// ---------------------------------------------------------------------------
// Tensor-core GEMM, cp.async 4-buffer pipeline (depth 2, 1 barrier/iter),
// raw fp32 in SMEM, precision applied at fragment load:
//   PREC==3  : 3xTF32 split (fp32-grade; routing-feeding stages)
//   PREC==16 : fp16 m16n8k16 (same 10-bit mantissa as tf32, 2x rate; experts)
// STAGE 0: x@fw1->g_h (relu)     STAGE 1: g_h@fw2->g_feats
// STAGE 2: g_feats@kw->g_pk
// STAGE 3: gather(g_feats)@ew1[e]->g_h1 (relu)
// STAGE 4: g_h1@ew2[e]->g_h2 (relu)    STAGE 5: g_h2@ew3[e]->g_eout
// Tile 128x128x32, 8 warps (warp tile 64x32).
// ---------------------------------------------------------------------------
#define TBK  32
#define NBUF 4

__device__ __forceinline__ float cvt_tf32(float x) {
    float r;
    asm("cvt.rna.tf32.f32 %0, %1;" : "=f"(r) : "f"(x));
    return r;
}
__device__ __forceinline__ uint32_t f16pk(float lo, float hi) {
    uint32_t r;
    asm("cvt.rn.f16x2.f32 %0, %1, %2;" : "=r"(r) : "f"(hi), "f"(lo));
    return r;
}
__device__ __forceinline__ void mma_tf32(float c[4],
                                         const uint32_t a[4],
                                         const uint32_t b[2]) {
    asm volatile(
        "mma.sync.aligned.m16n8k8.row.col.f32.tf32.tf32.f32 "
        "{%0,%1,%2,%3}, {%4,%5,%6,%7}, {%8,%9}, {%0,%1,%2,%3};"
        : "+f"(c[0]), "+f"(c[1]), "+f"(c[2]), "+f"(c[3])
        : "r"(a[0]), "r"(a[1]), "r"(a[2]), "r"(a[3]),
          "r"(b[0]), "r"(b[1]));
}
__device__ __forceinline__ void mma_f16(float c[4],
                                        const uint32_t a[4],
                                        const uint32_t b[2]) {
    asm volatile(
        "mma.sync.aligned.m16n8k16.row.col.f32.f16.f16.f32 "
        "{%0,%1,%2,%3}, {%4,%5,%6,%7}, {%8,%9}, {%0,%1,%2,%3};"
        : "+f"(c[0]), "+f"(c[1]), "+f"(c[2]), "+f"(c[3])
        : "r"(a[0]), "r"(a[1]), "r"(a[2]), "r"(a[3]),
          "r"(b[0]), "r"(b[1]));
}
__device__ __forceinline__ void cp16(void* dst, const void* src, bool valid) {
    uint32_t d = (uint32_t)__cvta_generic_to_shared(dst);
    int sz = valid ? 16 : 0;
    asm volatile("cp.async.cg.shared.global [%0], [%1], 16, %2;"
                 :: "r"(d), "l"(src), "r"(sz));
}

template<int STAGE, bool RELU, int PREC>
__global__ __launch_bounds__(256) void tgemm_k(const float* __restrict__ Aext,
                                               const float* __restrict__ Wg,
                                               const float* __restrict__ Biasg,
                                               int Mfull, int N, int Kd)
{
    extern __shared__ float sm[];
    float (*As)[128][36]  = (float(*)[128][36])sm;                       // NBUF x 18432B
    float (*Bs)[TBK][136] = (float(*)[TBK][136])(sm + NBUF * 128 * 36);  // NBUF x 17408B

    int M;
    const float* A;
    const float* W;
    const float* Bias;
    float* C;
    const int* gather = nullptr;

    if (STAGE == 0)      { A = Aext;    C = g_h;     M = Mfull; W = Wg; Bias = Biasg; }
    else if (STAGE == 1) { A = g_h;     C = g_feats; M = Mfull; W = Wg; Bias = Biasg; }
    else if (STAGE == 2) { A = g_feats; C = g_pk;    M = Mfull; W = Wg; Bias = Biasg; }
    else {
        int e  = blockIdx.z;
        int m0 = g_offsets[e];
        M = g_offsets[e + 1] - m0;
        W    = Wg    + (size_t)e * Kd * N;
        Bias = Biasg + (size_t)e * N;
        if (STAGE == 3)      { A = g_feats; gather = g_list + m0; C = g_h1   + (size_t)m0 * N; }
        else if (STAGE == 4) { A = g_h1  + (size_t)m0 * Kd;       C = g_h2   + (size_t)m0 * N; }
        else                 { A = g_h2  + (size_t)m0 * Kd;       C = g_eout + (size_t)m0 * N; }
    }

    const int tileM = blockIdx.y * 128;
    if (tileM >= M) return;
    const int tileN = blockIdx.x * 128;

    const int tid  = threadIdx.x;
    const int lane = tid & 31;
    const int wid  = tid >> 5;
    const int g    = lane >> 2;
    const int tig  = lane & 3;
    const int warpM = wid & 1;
    const int warpN = wid >> 1;

    // A row pointers / validity (rows fixed across k-iters)
    const float* aptr[4];
    bool av[4];
#pragma unroll
    for (int it = 0; it < 4; it++) {
        int r = (tid >> 3) + it * 32;
        int grow = tileM + r;
        bool v = (grow < M);
        size_t arow = 0;
        if (v) arow = (STAGE == 3) ? (size_t)gather[grow] : (size_t)grow;
        aptr[it] = A + arow * Kd + (tid & 7) * 4;
        av[it] = v;
    }
    const int bc = (tid & 31) * 4;
    const bool bv = (tileN + bc) < N;
    const int br = tid >> 5;

    float acc[4][4][4];
#pragma unroll
    for (int i = 0; i < 4; i++)
#pragma unroll
        for (int j = 0; j < 4; j++)
#pragma unroll
            for (int r = 0; r < 4; r++) acc[i][j][r] = 0.f;

    const int KT = Kd / TBK;

    auto load_tile = [&](int k0, int buf) {
#pragma unroll
        for (int it = 0; it < 4; it++) {
            int r = (tid >> 3) + it * 32;
            cp16(&As[buf][r][(tid & 7) * 4], aptr[it] + k0, av[it]);
        }
#pragma unroll
        for (int it = 0; it < 4; it++) {
            int r = br + it * 8;
            const float* src = W + (size_t)(k0 + r) * N + tileN + bc;
            cp16(&Bs[buf][r][bc], src, bv);
        }
        asm volatile("cp.async.commit_group;");
    };

    load_tile(0, 0);
    if (KT > 1) load_tile(TBK, 1);

    for (int kt = 0; kt < KT; kt++) {
        const int buf = kt & (NBUF - 1);
        if (kt + 2 < KT) {
            load_tile((kt + 2) * TBK, (kt + 2) & (NBUF - 1));
            asm volatile("cp.async.wait_group 2;");
        } else if (kt + 1 < KT) {
            asm volatile("cp.async.wait_group 1;");
        } else {
            asm volatile("cp.async.wait_group 0;");
        }
        __syncthreads();

        if (PREC == 16) {
            // fp16 m16n8k16: two k16 steps per k-tile
#pragma unroll
            for (int ks = 0; ks < 2; ks++) {
                const int k16 = ks * 16;
                uint32_t bf[4][2];
#pragma unroll
                for (int nf = 0; nf < 4; nf++) {
                    int n = warpN * 32 + nf * 8 + g;
                    float b0 = Bs[buf][k16 + 2 * tig    ][n];
                    float b1 = Bs[buf][k16 + 2 * tig + 1][n];
                    float b2 = Bs[buf][k16 + 2 * tig + 8][n];
                    float b3 = Bs[buf][k16 + 2 * tig + 9][n];
                    bf[nf][0] = f16pk(b0, b1);
                    bf[nf][1] = f16pk(b2, b3);
                }
#pragma unroll
                for (int mf = 0; mf < 4; mf++) {
                    int m = warpM * 64 + mf * 16 + g;
                    float2 a01 = *(const float2*)&As[buf][m    ][k16 + 2 * tig];
                    float2 a23 = *(const float2*)&As[buf][m + 8][k16 + 2 * tig];
                    float2 a45 = *(const float2*)&As[buf][m    ][k16 + 2 * tig + 8];
                    float2 a67 = *(const float2*)&As[buf][m + 8][k16 + 2 * tig + 8];
                    uint32_t af[4];
                    af[0] = f16pk(a01.x, a01.y);
                    af[1] = f16pk(a23.x, a23.y);
                    af[2] = f16pk(a45.x, a45.y);
                    af[3] = f16pk(a67.x, a67.y);
#pragma unroll
                    for (int nf = 0; nf < 4; nf++)
                        mma_f16(acc[mf][nf], af, bf[nf]);
                }
            }
        } else {
            // 3xTF32 split: C += Ahi*Bhi + Ahi*Blo + Alo*Bhi
#pragma unroll
            for (int ks = 0; ks < 4; ks++) {
                const int k8 = ks * 8;
                uint32_t bh[4][2], bl[4][2];
#pragma unroll
                for (int nf = 0; nf < 4; nf++) {
                    int n = warpN * 32 + nf * 8 + g;
                    float b0 = Bs[buf][k8 + tig    ][n];
                    float b1 = Bs[buf][k8 + tig + 4][n];
                    float h0 = cvt_tf32(b0), h1 = cvt_tf32(b1);
                    bh[nf][0] = __float_as_uint(h0);
                    bh[nf][1] = __float_as_uint(h1);
                    bl[nf][0] = __float_as_uint(cvt_tf32(b0 - h0));
                    bl[nf][1] = __float_as_uint(cvt_tf32(b1 - h1));
                }
#pragma unroll
                for (int mf = 0; mf < 4; mf++) {
                    int m = warpM * 64 + mf * 16 + g;
                    float afv[4];
                    afv[0] = As[buf][m    ][k8 + tig    ];
                    afv[1] = As[buf][m + 8][k8 + tig    ];
                    afv[2] = As[buf][m    ][k8 + tig + 4];
                    afv[3] = As[buf][m + 8][k8 + tig + 4];
                    uint32_t ah[4], al[4];
#pragma unroll
                    for (int r4 = 0; r4 < 4; r4++) {
                        float hi = cvt_tf32(afv[r4]);
                        ah[r4] = __float_as_uint(hi);
                        al[r4] = __float_as_uint(cvt_tf32(afv[r4] - hi));
                    }
#pragma unroll
                    for (int nf = 0; nf < 4; nf++) {
                        mma_tf32(acc[mf][nf], al, bh[nf]);
                        mma_tf32(acc[mf][nf], ah, bl[nf]);
                        mma_tf32(acc[mf][nf], ah, bh[nf]);
                    }
                }
            }
        }
        __syncthreads();
    }

    // --- epilogue: bias (+relu) + store ---
#pragma unroll
    for (int mf = 0; mf < 4; mf++) {
        int row0 = tileM + warpM * 64 + mf * 16 + g;
        int row1 = row0 + 8;
#pragma unroll
        for (int nf = 0; nf < 4; nf++) {
            int col0 = tileN + warpN * 32 + nf * 8 + tig * 2;
            int col1 = col0 + 1;
            float b0 = (col0 < N) ? Bias[col0] : 0.f;
            float b1 = (col1 < N) ? Bias[col1] : 0.f;
            float v00 = acc[mf][nf][0] + b0;
            float v01 = acc[mf][nf][1] + b1;
            float v10 = acc[mf][nf][2] + b0;
            float v11 = acc[mf][nf][3] + b1;
            if (RELU) {
                v00 = fmaxf(v00, 0.f); v01 = fmaxf(v01, 0.f);
                v10 = fmaxf(v10, 0.f); v11 = fmaxf(v11, 0.f);
            }
            if (row0 < M) {
                if (col0 < N) C[(size_t)row0 * N + col0] = v00;
                if (col1 < N) C[(size_t)row0 * N + col1] = v01;
            }
            if (row1 < M) {
                if (col0 < N) C[(size_t)row1 * N + col0] = v10;
                if (col1 < N) C[(size_t)row1 * N + col1] = v11;
            }
        }
    }
}

// ---------------------------------------------------------------------------
// keys normalization / routing / grouping / combine
// ---------------------------------------------------------------------------
__global__ void keysn_kernel(const float* __restrict__ keys)
{
    int e    = threadIdx.x >> 5;
    int lane = threadIdx.x & 31;
    if (e >= EDIM) return;
    float4 v = *(const float4*)(keys + e * KDIM + lane * 4);
    float ss = v.x * v.x + v.y * v.y + v.z * v.z + v.w * v.w;
#pragma unroll
    for (int o = 16; o; o >>= 1) ss += __shfl_xor_sync(0xffffffffu, ss, o);
    float inv = 1.f / fmaxf(sqrtf(ss), 1e-12f);
    float4 o4 = make_float4(v.x * inv, v.y * inv, v.z * inv, v.w * inv);
    *(float4*)(g_keysn + e * KDIM + lane * 4) = o4;
}

__global__ void zero_counts_kernel()
{
    if (threadIdx.x < EDIM) g_counts[threadIdx.x] = 0;
}

__global__ void router_kernel()
{
    int warp = threadIdx.x >> 5;
    int lane = threadIdx.x & 31;
    int t = blockIdx.x * 8 + warp;
    if (t >= BDIM) return;

    float4 v = *(const float4*)(g_pk + (size_t)t * KDIM + lane * 4);
    float ss = v.x * v.x + v.y * v.y + v.z * v.z + v.w * v.w;
#pragma unroll
    for (int o = 16; o; o >>= 1) ss += __shfl_xor_sync(0xffffffffu, ss, o);
    float inv = 1.f / fmaxf(sqrtf(ss), 1e-12f);

    float sims[EDIM];
#pragma unroll
    for (int e = 0; e < EDIM; e++) {
        float4 kv = *(const float4*)(g_keysn + e * KDIM + lane * 4);
        float d = v.x * kv.x + v.y * kv.y + v.z * kv.z + v.w * kv.w;
#pragma unroll
        for (int o = 16; o; o >>= 1) d += __shfl_xor_sync(0xffffffffu, d, o);
        sims[e] = d * inv;
    }

    if (lane == 0) {
        int i0 = 0; float v0 = sims[0];
#pragma unroll
        for (int e = 1; e < EDIM; e++) if (sims[e] > v0) { v0 = sims[e]; i0 = e; }
        int i1 = -1; float v1 = -1e30f;
#pragma unroll
        for (int e = 0; e < EDIM; e++) if (e != i0 && sims[e] > v1) { v1 = sims[e]; i1 = e; }

        float e1 = expf(v1 - v0);
        float s  = 1.f + e1;
        float w0 = 1.f / s;
        float w1 = e1 / s;

#pragma unroll
        for (int e = 0; e < EDIM; e++) {
            g_sim[t * EDIM + e] = sims[e];
            g_weights[t * EDIM + e] = (e == i0) ? w0 : ((e == i1) ? w1 : 0.f);
        }
        g_topi[t * TOPK + 0] = i0;
        g_topi[t * TOPK + 1] = i1;
        g_wslot[t * TOPK + 0] = w0;
        g_wslot[t * TOPK + 1] = w1;
        atomicAdd(&g_counts[i0], 1);
        atomicAdd(&g_counts[i1], 1);
    }
}

__global__ void scan_kernel()
{
    if (threadIdx.x == 0) {
        int off = 0;
        for (int e = 0; e < EDIM; e++) {
            g_offsets[e] = off;
            g_cursor[e]  = off;
            off += g_counts[e];
        }
        g_offsets[EDIM] = off;
    }
}

__global__ void scatter_kernel()
{
    int t = blockIdx.x * blockDim.x + threadIdx.x;
    if (t >= BDIM) return;
#pragma unroll
    for (int s = 0; s < TOPK; s++) {
        int e = g_topi[t * TOPK + s];
        int pos = atomicAdd(&g_cursor[e], 1);
        g_list[pos] = t;
        g_pos[t * TOPK + s] = pos;
    }
}

__global__ void combine_kernel(float* __restrict__ out)
{
    int t = blockIdx.x;
    float w0 = g_wslot[t * TOPK + 0];
    float w1 = g_wslot[t * TOPK + 1];
    size_t p0 = (size_t)g_pos[t * TOPK + 0];
    size_t p1 = (size_t)g_pos[t * TOPK + 1];
    for (int c = threadIdx.x; c < CDIM; c += blockDim.x)
        out[(size_t)t * CDIM + c] =
            w0 * g_eout[p0 * CDIM + c] + w1 * g_eout[p1 * CDIM + c];
}

__global__ void tail_writer_kernel(float* __restrict__ out, long long out_size)
{
    long long i = (long long)blockIdx.x * blockDim.x + threadIdx.x;
    const long long base_w = (long long)BDIM * CDIM;
    const long long n_w = BDIM * EDIM;
    const long long base_t = base_w + n_w;
    const long long n_t = BDIM * TOPK;
    const long long base_s = base_t + n_t;
    const long long n_s = BDIM * EDIM;
    if (i < n_w && base_w + i < out_size) out[base_w + i] = g_weights[i];
    if (i < n_t && base_t + i < out_size) out[base_t + i] = (float)g_topi[i];
    if (i < n_s && base_s + i < out_size) out[base_s + i] = g_sim[i];
}

// ---------------------------------------------------------------------------
// Launch
// ---------------------------------------------------------------------------
#define TG_SMEM (NBUF * (128 * 36 + TBK * 136) * (int)sizeof(float))  // 143360 B

extern "C" void kernel_launch(void* const* d_in, const int* in_sizes, int n_in,
                              void* d_out, int out_size)
{
    const float* x    = (const float*)d_in[0];
    const float* fw1  = (const float*)d_in[1];
    const float* fb1  = (const float*)d_in[2];
    const float* fw2  = (const float*)d_in[3];
    const float* fb2  = (const float*)d_in[4];
    const float* kw   = (const float*)d_in[5];
    const float* kb   = (const float*)d_in[6];
    const float* keys = (const float*)d_in[7];
    const float* ew1  = (const float*)d_in[8];
    const float* eb1  = (const float*)d_in[9];
    const float* ew2  = (const float*)d_in[10];
    const float* eb2  = (const float*)d_in[11];
    const float* ew3  = (const float*)d_in[12];
    const float* eb3  = (const float*)d_in[13];
    float* out = (float*)d_out;

    cudaFuncSetAttribute(tgemm_k<0, true,  3 >, cudaFuncAttributeMaxDynamicSharedMemorySize, TG_SMEM);
    cudaFuncSetAttribute(tgemm_k<1, false, 3 >, cudaFuncAttributeMaxDynamicSharedMemorySize, TG_SMEM);
    cudaFuncSetAttribute(tgemm_k<2, false, 3 >, cudaFuncAttributeMaxDynamicSharedMemorySize, TG_SMEM);
    cudaFuncSetAttribute(tgemm_k<3, true,  16>, cudaFuncAttributeMaxDynamicSharedMemorySize, TG_SMEM);
    cudaFuncSetAttribute(tgemm_k<4, true,  16>, cudaFuncAttributeMaxDynamicSharedMemorySize, TG_SMEM);
    cudaFuncSetAttribute(tgemm_k<5, false, 16>, cudaFuncAttributeMaxDynamicSharedMemorySize, TG_SMEM);

    dim3 blk(256);

    keysn_kernel<<<1, 256>>>(keys);
    zero_counts_kernel<<<1, 32>>>();

    // feature extractor + router projection: 3xTF32 split (fp32-grade)
    tgemm_k<0, true,  3><<<dim3(HDIM / 128, BDIM / 128, 1), blk, TG_SMEM>>>(x,       fw1, fb1, BDIM, HDIM, DDIM);
    tgemm_k<1, false, 3><<<dim3(HDIM / 128, BDIM / 128, 1), blk, TG_SMEM>>>(nullptr, fw2, fb2, BDIM, HDIM, HDIM);
    tgemm_k<2, false, 3><<<dim3(1,          BDIM / 128, 1), blk, TG_SMEM>>>(nullptr, kw,  kb,  BDIM, KDIM, HDIM);

    router_kernel<<<BDIM / 8, 256>>>();
    scan_kernel<<<1, 32>>>();
    scatter_kernel<<<(BDIM + 255) / 256, 256>>>();

    // expert MLPs: fp16 tensor cores on grouped (top-2 only) rows
    tgemm_k<3, true,  16><<<dim3(HDIM / 128,         BDIM / 128, EDIM), blk, TG_SMEM>>>(nullptr, ew1, eb1, 0, HDIM,  HDIM);
    tgemm_k<4, true,  16><<<dim3(H2DIM / 128,        BDIM / 128, EDIM), blk, TG_SMEM>>>(nullptr, ew2, eb2, 0, H2DIM, HDIM);
    tgemm_k<5, false, 16><<<dim3((CDIM + 127) / 128, BDIM / 128, EDIM), blk, TG_SMEM>>>(nullptr, ew3, eb3, 0, CDIM,  H2DIM);

    combine_kernel<<<BDIM, 256>>>(out);
    tail_writer_kernel<<<(BDIM * EDIM + 255) / 256, 256>>>(out, (long long)out_size);
}

// round 7
// speedup vs baseline: 1.3201x; 1.3201x over previous
#include <cuda_runtime.h>
#include <cuda_fp16.h>
#include <math.h>
#include <stdint.h>

// ---------------------------------------------------------------------------
// Problem constants
// ---------------------------------------------------------------------------
#define BDIM   8192
#define DDIM   1024
#define HDIM   2048
#define H2DIM  1024
#define CDIM   1000
#define KDIM   128
#define EDIM   8
#define TOPK   2
#define MAXROWS (BDIM * TOPK)

// ---------------------------------------------------------------------------
// Scratch (device globals — no allocation allowed)
// ---------------------------------------------------------------------------
__device__ float  g_h    [(size_t)BDIM * HDIM];
__device__ float  g_feats[(size_t)BDIM * HDIM];
__device__ __half g_featsh[(size_t)BDIM * HDIM];
__device__ float  g_pk   [(size_t)BDIM * KDIM];
__device__ float  g_keysn[EDIM * KDIM];
__device__ float  g_sim  [BDIM * EDIM];
__device__ float  g_weights[BDIM * EDIM];
__device__ float  g_wslot[BDIM * TOPK];
__device__ int    g_topi [BDIM * TOPK];
__device__ int    g_counts[EDIM];
__device__ int    g_offsets[EDIM + 1];
__device__ int    g_cursor[EDIM];
__device__ int    g_list [MAXROWS];
__device__ int    g_pos  [BDIM * TOPK];
__device__ __half g_h1h  [(size_t)MAXROWS * HDIM];
__device__ __half g_h2h  [(size_t)MAXROWS * H2DIM];
__device__ float  g_eout [(size_t)MAXROWS * CDIM];
// transposed half expert weights: [E][N][K]
__device__ __half g_ew1h [(size_t)EDIM * HDIM  * HDIM];
__device__ __half g_ew2h [(size_t)EDIM * H2DIM * HDIM];
__device__ __half g_ew3h [(size_t)EDIM * CDIM  * H2DIM];

// ---------------------------------------------------------------------------
// helpers
// ---------------------------------------------------------------------------
__device__ __forceinline__ float cvt_tf32(float x) {
    float r;
    asm("cvt.rna.tf32.f32 %0, %1;" : "=f"(r) : "f"(x));
    return r;
}
__device__ __forceinline__ void mma_tf32(float c[4],
                                         const uint32_t a[4],
                                         const uint32_t b[2]) {
    asm volatile(
        "mma.sync.aligned.m16n8k8.row.col.f32.tf32.tf32.f32 "
        "{%0,%1,%2,%3}, {%4,%5,%6,%7}, {%8,%9}, {%0,%1,%2,%3};"
        : "+f"(c[0]), "+f"(c[1]), "+f"(c[2]), "+f"(c[3])
        : "r"(a[0]), "r"(a[1]), "r"(a[2]), "r"(a[3]),
          "r"(b[0]), "r"(b[1]));
}
__device__ __forceinline__ void mma_f16(float c[4],
                                        const uint32_t a[4],
                                        const uint32_t b[2]) {
    asm volatile(
        "mma.sync.aligned.m16n8k16.row.col.f32.f16.f16.f32 "
        "{%0,%1,%2,%3}, {%4,%5,%6,%7}, {%8,%9}, {%0,%1,%2,%3};"
        : "+f"(c[0]), "+f"(c[1]), "+f"(c[2]), "+f"(c[3])
        : "r"(a[0]), "r"(a[1]), "r"(a[2]), "r"(a[3]),
          "r"(b[0]), "r"(b[1]));
}
__device__ __forceinline__ void cp16(void* dst, const void* src, bool valid) {
    uint32_t d = (uint32_t)__cvta_generic_to_shared(dst);
    int sz = valid ? 16 : 0;
    asm volatile("cp.async.cg.shared.global [%0], [%1], 16, %2;"
                 :: "r"(d), "l"(src), "r"(sz));
}

// ---------------------------------------------------------------------------
// Weight convert+transpose: W[K][N] fp32 -> Wt[N][K] half   (per expert z)
// ---------------------------------------------------------------------------
__global__ void wconv_k(const float* __restrict__ Wg, __half* __restrict__ Wtg,
                        int K, int N)
{
    const float* W  = Wg  + (size_t)blockIdx.z * K * N;
    __half*      Wt = Wtg + (size_t)blockIdx.z * N * K;
    __shared__ float t[32][33];
    int k0 = blockIdx.y * 32;
    int n0 = blockIdx.x * 32;
#pragma unroll
    for (int j = 0; j < 4; j++) {
        int k = k0 + threadIdx.y + j * 8;
        int n = n0 + threadIdx.x;
        if (n < N) t[threadIdx.y + j * 8][threadIdx.x] = W[(size_t)k * N + n];
    }
    __syncthreads();
#pragma unroll
    for (int j = 0; j < 4; j++) {
        int n = n0 + threadIdx.y + j * 8;
        int k = k0 + threadIdx.x;
        if (n < N) Wt[(size_t)n * K + k] = __float2half(t[threadIdx.x][threadIdx.y + j * 8]);
    }
}

// ---------------------------------------------------------------------------
// 3xTF32-split GEMM (R5-proven): stages 0,1,2 (routing path, fp32-grade)
//   STAGE 0: x@fw1->g_h (relu)   STAGE 1: g_h@fw2->g_feats (+half copy)
//   STAGE 2: g_feats@kw->g_pk
// Tile 128x128x32, NBUF=2, 8 warps (warp tile 64x32).
// ---------------------------------------------------------------------------
#define TBK 32

template<int STAGE, bool RELU>
__global__ __launch_bounds__(256) void tgemm_k(const float* __restrict__ Aext,
                                               const float* __restrict__ W,
                                               const float* __restrict__ Bias,
                                               int M, int N, int Kd)
{
    extern __shared__ float sm[];
    float (*As)[128][36]  = (float(*)[128][36])sm;
    float (*Bs)[TBK][136] = (float(*)[TBK][136])(sm + 2 * 128 * 36);

    const float* A;
    float* C;
    if (STAGE == 0)      { A = Aext;    C = g_h;     }
    else if (STAGE == 1) { A = g_h;     C = g_feats; }
    else                 { A = g_feats; C = g_pk;    }

    const int tileM = blockIdx.y * 128;
    if (tileM >= M) return;
    const int tileN = blockIdx.x * 128;

    const int tid  = threadIdx.x;
    const int lane = tid & 31;
    const int wid  = tid >> 5;
    const int g    = lane >> 2;
    const int tig  = lane & 3;
    const int warpM = wid & 1;
    const int warpN = wid >> 1;

    const float* aptr[4];
    bool av[4];
#pragma unroll
    for (int it = 0; it < 4; it++) {
        int r = (tid >> 3) + it * 32;
        int grow = tileM + r;
        av[it] = (grow < M);
        aptr[it] = A + (size_t)(av[it] ? grow : 0) * Kd + (tid & 7) * 4;
    }
    const int bc = (tid & 31) * 4;
    const bool bv = (tileN + bc) < N;
    const int br = tid >> 5;

    float acc[4][4][4];
#pragma unroll
    for (int i = 0; i < 4; i++)
#pragma unroll
        for (int j = 0; j < 4; j++)
#pragma unroll
            for (int r = 0; r < 4; r++) acc[i][j][r] = 0.f;

    const int KT = Kd / TBK;

    auto load_tile = [&](int k0, int buf) {
#pragma unroll
        for (int it = 0; it < 4; it++) {
            int r = (tid >> 3) + it * 32;
            cp16(&As[buf][r][(tid & 7) * 4], aptr[it] + k0, av[it]);
        }
#pragma unroll
        for (int it = 0; it < 4; it++) {
            int r = br + it * 8;
            const float* src = W + (size_t)(k0 + r) * N + tileN + bc;
            cp16(&Bs[buf][r][bc], src, bv);
        }
        asm volatile("cp.async.commit_group;");
    };

    load_tile(0, 0);

    for (int kt = 0; kt < KT; kt++) {
        const int buf = kt & 1;
        if (kt + 1 < KT) {
            load_tile((kt + 1) * TBK, (kt + 1) & 1);
            asm volatile("cp.async.wait_group 1;");
        } else {
            asm volatile("cp.async.wait_group 0;");
        }
        __syncthreads();

#pragma unroll
        for (int ks = 0; ks < 4; ks++) {
            const int k8 = ks * 8;
            uint32_t bh[4][2], bl[4][2];
#pragma unroll
            for (int nf = 0; nf < 4; nf++) {
                int n = warpN * 32 + nf * 8 + g;
                float b0 = Bs[buf][k8 + tig    ][n];
                float b1 = Bs[buf][k8 + tig + 4][n];
                float h0 = cvt_tf32(b0), h1 = cvt_tf32(b1);
                bh[nf][0] = __float_as_uint(h0);
                bh[nf][1] = __float_as_uint(h1);
                bl[nf][0] = __float_as_uint(cvt_tf32(b0 - h0));
                bl[nf][1] = __float_as_uint(cvt_tf32(b1 - h1));
            }
#pragma unroll
            for (int mf = 0; mf < 4; mf++) {
                int m = warpM * 64 + mf * 16 + g;
                float afv[4];
                afv[0] = As[buf][m    ][k8 + tig    ];
                afv[1] = As[buf][m + 8][k8 + tig    ];
                afv[2] = As[buf][m    ][k8 + tig + 4];
                afv[3] = As[buf][m + 8][k8 + tig + 4];
                uint32_t ah[4], al[4];
#pragma unroll
                for (int r4 = 0; r4 < 4; r4++) {
                    float hi = cvt_tf32(afv[r4]);
                    ah[r4] = __float_as_uint(hi);
                    al[r4] = __float_as_uint(cvt_tf32(afv[r4] - hi));
                }
#pragma unroll
                for (int nf = 0; nf < 4; nf++) {
                    mma_tf32(acc[mf][nf], al, bh[nf]);
                    mma_tf32(acc[mf][nf], ah, bl[nf]);
                    mma_tf32(acc[mf][nf], ah, bh[nf]);
                }
            }
        }
        __syncthreads();
    }

#pragma unroll
    for (int mf = 0; mf < 4; mf++) {
        int row0 = tileM + warpM * 64 + mf * 16 + g;
        int row1 = row0 + 8;
#pragma unroll
        for (int nf = 0; nf < 4; nf++) {
            int col0 = tileN + warpN * 32 + nf * 8 + tig * 2;
            int col1 = col0 + 1;
            float b0 = (col0 < N) ? Bias[col0] : 0.f;
            float b1 = (col1 < N) ? Bias[col1] : 0.f;
            float v00 = acc[mf][nf][0] + b0;
            float v01 = acc[mf][nf][1] + b1;
            float v10 = acc[mf][nf][2] + b0;
            float v11 = acc[mf][nf][3] + b1;
            if (RELU) {
                v00 = fmaxf(v00, 0.f); v01 = fmaxf(v01, 0.f);
                v10 = fmaxf(v10, 0.f); v11 = fmaxf(v11, 0.f);
            }
            if (row0 < M) {
                if (col0 < N) {
                    C[(size_t)row0 * N + col0] = v00;
                    if (STAGE == 1) g_featsh[(size_t)row0 * N + col0] = __float2half(v00);
                }
                if (col1 < N) {
                    C[(size_t)row0 * N + col1] = v01;
                    if (STAGE == 1) g_featsh[(size_t)row0 * N + col1] = __float2half(v01);
                }
            }
            if (row1 < M) {
                if (col0 < N) {
                    C[(size_t)row1 * N + col0] = v10;
                    if (STAGE == 1) g_featsh[(size_t)row1 * N + col0] = __float2half(v10);
                }
                if (col1 < N) {
                    C[(size_t)row1 * N + col1] = v11;
                    if (STAGE == 1) g_featsh[(size_t)row1 * N + col1] = __float2half(v11);
                }
            }
        }
    }
}

// ---------------------------------------------------------------------------
// Pure fp16 expert GEMM. A: half k-major. B: transposed half weights [N][K].
// No conversion in the loop; every fragment word is one LDS.32, conflict-free.
// Tile 128x128x64, NBUF=2, 8 warps (warp tile 64x32), mma.m16n8k16.
//   STAGE 3: gather(g_featsh)@ew1h[e] -> g_h1h (relu)
//   STAGE 4: g_h1h@ew2h[e] -> g_h2h (relu)
//   STAGE 5: g_h2h@ew3h[e] -> g_eout (fp32)
// ---------------------------------------------------------------------------
#define HBK 64

template<int STAGE, bool RELU>
__global__ __launch_bounds__(256) void hgemm_k(const __half* __restrict__ Wt,
                                               const float* __restrict__ Biasg,
                                               int N, int Kd)
{
    extern __shared__ __half smh[];
    __half (*Ah)[128][72] = (__half(*)[128][72])smh;                      // 2 x 18432B
    __half (*Bh)[128][72] = (__half(*)[128][72])(smh + 2 * 128 * 72);     // 2 x 18432B

    const int e  = blockIdx.z;
    const int m0 = g_offsets[e];
    const int M  = g_offsets[e + 1] - m0;

    const int tileM = blockIdx.y * 128;
    if (tileM >= M) return;
    const int tileN = blockIdx.x * 128;

    const __half* B = Wt + (size_t)e * N * Kd;
    const float* Bias = Biasg + (size_t)e * N;

    const __half* A;
    __half* Ch = nullptr;
    float*  Cf = nullptr;
    const int* gather = nullptr;
    if (STAGE == 3)      { A = g_featsh; gather = g_list + m0; Ch = g_h1h + (size_t)m0 * N; }
    else if (STAGE == 4) { A = g_h1h + (size_t)m0 * Kd;        Ch = g_h2h + (size_t)m0 * N; }
    else                 { A = g_h2h + (size_t)m0 * Kd;        Cf = g_eout + (size_t)m0 * N; }

    const int tid  = threadIdx.x;
    const int lane = tid & 31;
    const int wid  = tid >> 5;
    const int g    = lane >> 2;
    const int tig  = lane & 3;
    const int warpM = wid & 1;
    const int warpN = wid >> 1;

    // A row pointers (8 halves = 16B per cp; 8 threads per 64-half row)
    const __half* aptr[4];
    bool av[4];
#pragma unroll
    for (int it = 0; it < 4; it++) {
        int r = (tid >> 3) + it * 32;
        int grow = tileM + r;
        av[it] = (grow < M);
        size_t arow = 0;
        if (av[it]) arow = (STAGE == 3) ? (size_t)gather[grow] : (size_t)grow;
        aptr[it] = A + arow * Kd + (tid & 7) * 8;
    }
    // B row pointers (n-rows of transposed weights)
    const __half* bptr[4];
    bool bvv[4];
#pragma unroll
    for (int it = 0; it < 4; it++) {
        int r = (tid >> 3) + it * 32;
        int gn = tileN + r;
        bvv[it] = (gn < N);
        bptr[it] = B + (size_t)(bvv[it] ? gn : 0) * Kd + (tid & 7) * 8;
    }

    float acc[4][4][4];
#pragma unroll
    for (int i = 0; i < 4; i++)
#pragma unroll
        for (int j = 0; j < 4; j++)
#pragma unroll
            for (int r = 0; r < 4; r++) acc[i][j][r] = 0.f;

    const int KT = Kd / HBK;

    auto load_tile = [&](int k0, int buf) {
#pragma unroll
        for (int it = 0; it < 4; it++) {
            int r = (tid >> 3) + it * 32;
            cp16(&Ah[buf][r][(tid & 7) * 8], aptr[it] + k0, av[it]);
        }
#pragma unroll
        for (int it = 0; it < 4; it++) {
            int r = (tid >> 3) + it * 32;
            cp16(&Bh[buf][r][(tid & 7) * 8], bptr[it] + k0, bvv[it]);
        }
        asm volatile("cp.async.commit_group;");
    };

    load_tile(0, 0);

    for (int kt = 0; kt < KT; kt++) {
        const int buf = kt & 1;
        if (kt + 1 < KT) {
            load_tile((kt + 1) * HBK, (kt + 1) & 1);
            asm volatile("cp.async.wait_group 1;");
        } else {
            asm volatile("cp.async.wait_group 0;");
        }
        __syncthreads();

#pragma unroll
        for (int ks = 0; ks < 4; ks++) {
            const int k16 = ks * 16;
            uint32_t bf[4][2];
#pragma unroll
            for (int nf = 0; nf < 4; nf++) {
                int n = warpN * 32 + nf * 8 + g;
                bf[nf][0] = *(const uint32_t*)&Bh[buf][n][k16 + 2 * tig    ];
                bf[nf][1] = *(const uint32_t*)&Bh[buf][n][k16 + 2 * tig + 8];
            }
#pragma unroll
            for (int mf = 0; mf < 4; mf++) {
                int m = warpM * 64 + mf * 16 + g;
                uint32_t af[4];
                af[0] = *(const uint32_t*)&Ah[buf][m    ][k16 + 2 * tig    ];
                af[1] = *(const uint32_t*)&Ah[buf][m + 8][k16 + 2 * tig    ];
                af[2] = *(const uint32_t*)&Ah[buf][m    ][k16 + 2 * tig + 8];
                af[3] = *(const uint32_t*)&Ah[buf][m + 8][k16 + 2 * tig + 8];
#pragma unroll
                for (int nf = 0; nf < 4; nf++)
                    mma_f16(acc[mf][nf], af, bf[nf]);
            }
        }
        __syncthreads();
    }

    // --- epilogue ---
#pragma unroll
    for (int mf = 0; mf < 4; mf++) {
        int row0 = tileM + warpM * 64 + mf * 16 + g;
        int row1 = row0 + 8;
#pragma unroll
        for (int nf = 0; nf < 4; nf++) {
            int col0 = tileN + warpN * 32 + nf * 8 + tig * 2;
            int col1 = col0 + 1;
            float b0 = (col0 < N) ? Bias[col0] : 0.f;
            float b1 = (col1 < N) ? Bias[col1] : 0.f;
            float v00 = acc[mf][nf][0] + b0;
            float v01 = acc[mf][nf][1] + b1;
            float v10 = acc[mf][nf][2] + b0;
            float v11 = acc[mf][nf][3] + b1;
            if (RELU) {
                v00 = fmaxf(v00, 0.f); v01 = fmaxf(v01, 0.f);
                v10 = fmaxf(v10, 0.f); v11 = fmaxf(v11, 0.f);
            }
            if (STAGE == 5) {
                if (row0 < M) {
                    if (col0 < N) Cf[(size_t)row0 * N + col0] = v00;
                    if (col1 < N) Cf[(size_t)row0 * N + col1] = v01;
                }
                if (row1 < M) {
                    if (col0 < N) Cf[(size_t)row1 * N + col0] = v10;
                    if (col1 < N) Cf[(size_t)row1 * N + col1] = v11;
                }
            } else {
                if (row0 < M) {
                    if (col0 < N) Ch[(size_t)row0 * N + col0] = __float2half(v00);
                    if (col1 < N) Ch[(size_t)row0 * N + col1] = __float2half(v01);
                }
                if (row1 < M) {
                    if (col0 < N) Ch[(size_t)row1 * N + col0] = __float2half(v10);
                    if (col1 < N) Ch[(size_t)row1 * N + col1] = __float2half(v11);
                }
            }
        }
    }
}

// ---------------------------------------------------------------------------
// keys normalization / routing / grouping / combine
// ---------------------------------------------------------------------------
__global__ void keysn_kernel(const float* __restrict__ keys)
{
    int e    = threadIdx.x >> 5;
    int lane = threadIdx.x & 31;
    if (e >= EDIM) return;
    float4 v = *(const float4*)(keys + e * KDIM + lane * 4);
    float ss = v.x * v.x + v.y * v.y + v.z * v.z + v.w * v.w;
#pragma unroll
    for (int o = 16; o; o >>= 1) ss += __shfl_xor_sync(0xffffffffu, ss, o);
    float inv = 1.f / fmaxf(sqrtf(ss), 1e-12f);
    float4 o4 = make_float4(v.x * inv, v.y * inv, v.z * inv, v.w * inv);
    *(float4*)(g_keysn + e * KDIM + lane * 4) = o4;
}

__global__ void zero_counts_kernel()
{
    if (threadIdx.x < EDIM) g_counts[threadIdx.x] = 0;
}

__global__ void router_kernel()
{
    int warp = threadIdx.x >> 5;
    int lane = threadIdx.x & 31;
    int t = blockIdx.x * 8 + warp;
    if (t >= BDIM) return;

    float4 v = *(const float4*)(g_pk + (size_t)t * KDIM + lane * 4);
    float ss = v.x * v.x + v.y * v.y + v.z * v.z + v.w * v.w;
#pragma unroll
    for (int o = 16; o; o >>= 1) ss += __shfl_xor_sync(0xffffffffu, ss, o);
    float inv = 1.f / fmaxf(sqrtf(ss), 1e-12f);

    float sims[EDIM];
#pragma unroll
    for (int e = 0; e < EDIM; e++) {
        float4 kv = *(const float4*)(g_keysn + e * KDIM + lane * 4);
        float d = v.x * kv.x + v.y * kv.y + v.z * kv.z + v.w * kv.w;
#pragma unroll
        for (int o = 16; o; o >>= 1) d += __shfl_xor_sync(0xffffffffu, d, o);
        sims[e] = d * inv;
    }

    if (lane == 0) {
        int i0 = 0; float v0 = sims[0];
#pragma unroll
        for (int e = 1; e < EDIM; e++) if (sims[e] > v0) { v0 = sims[e]; i0 = e; }
        int i1 = -1; float v1 = -1e30f;
#pragma unroll
        for (int e = 0; e < EDIM; e++) if (e != i0 && sims[e] > v1) { v1 = sims[e]; i1 = e; }

        float e1 = expf(v1 - v0);
        float s  = 1.f + e1;
        float w0 = 1.f / s;
        float w1 = e1 / s;

#pragma unroll
        for (int e = 0; e < EDIM; e++) {
            g_sim[t * EDIM + e] = sims[e];
            g_weights[t * EDIM + e] = (e == i0) ? w0 : ((e == i1) ? w1 : 0.f);
        }
        g_topi[t * TOPK + 0] = i0;
        g_topi[t * TOPK + 1] = i1;
        g_wslot[t * TOPK + 0] = w0;
        g_wslot[t * TOPK + 1] = w1;
        atomicAdd(&g_counts[i0], 1);
        atomicAdd(&g_counts[i1], 1);
    }
}

__global__ void scan_kernel()
{
    if (threadIdx.x == 0) {
        int off = 0;
        for (int e = 0; e < EDIM; e++) {
            g_offsets[e] = off;
            g_cursor[e]  = off;
            off += g_counts[e];
        }
        g_offsets[EDIM] = off;
    }
}

__global__ void scatter_kernel()
{
    int t = blockIdx.x * blockDim.x + threadIdx.x;
    if (t >= BDIM) return;
#pragma unroll
    for (int s = 0; s < TOPK; s++) {
        int e = g_topi[t * TOPK + s];
        int pos = atomicAdd(&g_cursor[e], 1);
        g_list[pos] = t;
        g_pos[t * TOPK + s] = pos;
    }
}

__global__ void combine_kernel(float* __restrict__ out)
{
    int t = blockIdx.x;
    float w0 = g_wslot[t * TOPK + 0];
    float w1 = g_wslot[t * TOPK + 1];
    size_t p0 = (size_t)g_pos[t * TOPK + 0];
    size_t p1 = (size_t)g_pos[t * TOPK + 1];
    for (int c = threadIdx.x; c < CDIM; c += blockDim.x)
        out[(size_t)t * CDIM + c] =
            w0 * g_eout[p0 * CDIM + c] + w1 * g_eout[p1 * CDIM + c];
}

__global__ void tail_writer_kernel(float* __restrict__ out, long long out_size)
{
    long long i = (long long)blockIdx.x * blockDim.x + threadIdx.x;
    const long long base_w = (long long)BDIM * CDIM;
    const long long n_w = BDIM * EDIM;
    const long long base_t = base_w + n_w;
    const long long n_t = BDIM * TOPK;
    const long long base_s = base_t + n_t;
    const long long n_s = BDIM * EDIM;
    if (i < n_w && base_w + i < out_size) out[base_w + i] = g_weights[i];
    if (i < n_t && base_t + i < out_size) out[base_t + i] = (float)g_topi[i];
    if (i < n_s && base_s + i < out_size) out[base_s + i] = g_sim[i];
}

// ---------------------------------------------------------------------------
// Launch
// ---------------------------------------------------------------------------
#define TG_SMEM (2 * (128 * 36 + TBK * 136) * (int)sizeof(float))   // 71680 B
#define HG_SMEM (2 * 2 * 128 * 72 * (int)sizeof(__half))            // 73728 B

extern "C" void kernel_launch(void* const* d_in, const int* in_sizes, int n_in,
                              void* d_out, int out_size)
{
    const float* x    = (const float*)d_in[0];
    const float* fw1  = (const float*)d_in[1];
    const float* fb1  = (const float*)d_in[2];
    const float* fw2  = (const float*)d_in[3];
    const float* fb2  = (const float*)d_in[4];
    const float* kw   = (const float*)d_in[5];
    const float* kb   = (const float*)d_in[6];
    const float* keys = (const float*)d_in[7];
    const float* ew1  = (const float*)d_in[8];
    const float* eb1  = (const float*)d_in[9];
    const float* ew2  = (const float*)d_in[10];
    const float* eb2  = (const float*)d_in[11];
    const float* ew3  = (const float*)d_in[12];
    const float* eb3  = (const float*)d_in[13];
    float* out = (float*)d_out;

    cudaFuncSetAttribute(tgemm_k<0, true >, cudaFuncAttributeMaxDynamicSharedMemorySize, TG_SMEM);
    cudaFuncSetAttribute(tgemm_k<1, false>, cudaFuncAttributeMaxDynamicSharedMemorySize, TG_SMEM);
    cudaFuncSetAttribute(tgemm_k<2, false>, cudaFuncAttributeMaxDynamicSharedMemorySize, TG_SMEM);
    cudaFuncSetAttribute(hgemm_k<3, true >, cudaFuncAttributeMaxDynamicSharedMemorySize, HG_SMEM);
    cudaFuncSetAttribute(hgemm_k<4, true >, cudaFuncAttributeMaxDynamicSharedMemorySize, HG_SMEM);
    cudaFuncSetAttribute(hgemm_k<5, false>, cudaFuncAttributeMaxDynamicSharedMemorySize, HG_SMEM);

    dim3 blk(256);
    dim3 tblk(32, 8);

    // one-time (per launch) weight convert+transpose to half [E][N][K]
    __half* ew1h; cudaGetSymbolAddress((void**)&ew1h, g_ew1h);
    __half* ew2h; cudaGetSymbolAddress((void**)&ew2h, g_ew2h);
    __half* ew3h; cudaGetSymbolAddress((void**)&ew3h, g_ew3h);
    wconv_k<<<dim3(HDIM / 32,              HDIM / 32,  EDIM), tblk>>>(ew1, ew1h, HDIM,  HDIM);
    wconv_k<<<dim3(H2DIM / 32,             HDIM / 32,  EDIM), tblk>>>(ew2, ew2h, HDIM,  H2DIM);
    wconv_k<<<dim3((CDIM + 31) / 32,       H2DIM / 32, EDIM), tblk>>>(ew3, ew3h, H2DIM, CDIM);

    keysn_kernel<<<1, 256>>>(keys);
    zero_counts_kernel<<<1, 32>>>();

    // feature extractor + router projection: 3xTF32 split (fp32-grade)
    tgemm_k<0, true ><<<dim3(HDIM / 128, BDIM / 128), blk, TG_SMEM>>>(x,       fw1, fb1, BDIM, HDIM, DDIM);
    tgemm_k<1, false><<<dim3(HDIM / 128, BDIM / 128), blk, TG_SMEM>>>(nullptr, fw2, fb2, BDIM, HDIM, HDIM);
    tgemm_k<2, false><<<dim3(1,          BDIM / 128), blk, TG_SMEM>>>(nullptr, kw,  kb,  BDIM, KDIM, HDIM);

    router_kernel<<<BDIM / 8, 256>>>();
    scan_kernel<<<1, 32>>>();
    scatter_kernel<<<(BDIM + 255) / 256, 256>>>();

    // expert MLPs: pure fp16 tensor-core GEMMs on grouped rows
    hgemm_k<3, true ><<<dim3(HDIM / 128,         BDIM / 128, EDIM), blk, HG_SMEM>>>(ew1h, eb1, HDIM,  HDIM);
    hgemm_k<4, true ><<<dim3(H2DIM / 128,        BDIM / 128, EDIM), blk, HG_SMEM>>>(ew2h, eb2, H2DIM, HDIM);
    hgemm_k<5, false><<<dim3((CDIM + 127) / 128, BDIM / 128, EDIM), blk, HG_SMEM>>>(ew3h, eb3, CDIM,  H2DIM);

    combine_kernel<<<BDIM, 256>>>(out);
    tail_writer_kernel<<<(BDIM * EDIM + 255) / 256, 256>>>(out, (long long)out_size);
}

// round 8
// speedup vs baseline: 1.7360x; 1.3151x over previous
#include <cuda_runtime.h>
#include <cuda_fp16.h>
#include <math.h>
#include <stdint.h>

// ---------------------------------------------------------------------------
// Problem constants
// ---------------------------------------------------------------------------
#define BDIM   8192
#define DDIM   1024
#define HDIM   2048
#define H2DIM  1024
#define CDIM   1000
#define KDIM   128
#define EDIM   8
#define TOPK   2
#define MAXROWS (BDIM * TOPK)

// ---------------------------------------------------------------------------
// Scratch (device globals — no allocation allowed)
// ---------------------------------------------------------------------------
__device__ __half g_xhi  [(size_t)BDIM * DDIM];
__device__ __half g_xlo  [(size_t)BDIM * DDIM];
__device__ __half g_hhi  [(size_t)BDIM * HDIM];
__device__ __half g_hlo  [(size_t)BDIM * HDIM];
__device__ __half g_featshi[(size_t)BDIM * HDIM];
__device__ __half g_featslo[(size_t)BDIM * HDIM];
__device__ float  g_pk   [(size_t)BDIM * KDIM];
__device__ float  g_keysn[EDIM * KDIM];
__device__ float  g_sim  [BDIM * EDIM];
__device__ float  g_weights[BDIM * EDIM];
__device__ float  g_wslot[BDIM * TOPK];
__device__ int    g_topi [BDIM * TOPK];
__device__ int    g_counts[EDIM];
__device__ int    g_offsets[EDIM + 1];
__device__ int    g_cursor[EDIM];
__device__ int    g_list [MAXROWS];
__device__ int    g_pos  [BDIM * TOPK];
__device__ __half g_h1h  [(size_t)MAXROWS * HDIM];
__device__ __half g_h2h  [(size_t)MAXROWS * H2DIM];
__device__ float  g_eout [(size_t)MAXROWS * CDIM];
// transposed half weights
__device__ __half g_fw1hi[(size_t)HDIM * DDIM];   // [H][D]
__device__ __half g_fw1lo[(size_t)HDIM * DDIM];
__device__ __half g_fw2hi[(size_t)HDIM * HDIM];   // [H][H]
__device__ __half g_fw2lo[(size_t)HDIM * HDIM];
__device__ __half g_kwhi [(size_t)KDIM * HDIM];   // [K][H]
__device__ __half g_kwlo [(size_t)KDIM * HDIM];
__device__ __half g_ew1h [(size_t)EDIM * HDIM  * HDIM];
__device__ __half g_ew2h [(size_t)EDIM * H2DIM * HDIM];
__device__ __half g_ew3h [(size_t)EDIM * CDIM  * H2DIM];

#define LO_SCALE 4096.0f
#define LO_INV   (1.0f / 4096.0f)

// ---------------------------------------------------------------------------
// helpers
// ---------------------------------------------------------------------------
__device__ __forceinline__ void mma_f16(float c[4],
                                        const uint32_t a[4],
                                        const uint32_t b[2]) {
    asm volatile(
        "mma.sync.aligned.m16n8k16.row.col.f32.f16.f16.f32 "
        "{%0,%1,%2,%3}, {%4,%5,%6,%7}, {%8,%9}, {%0,%1,%2,%3};"
        : "+f"(c[0]), "+f"(c[1]), "+f"(c[2]), "+f"(c[3])
        : "r"(a[0]), "r"(a[1]), "r"(a[2]), "r"(a[3]),
          "r"(b[0]), "r"(b[1]));
}
__device__ __forceinline__ void cp16(void* dst, const void* src, bool valid) {
    uint32_t d = (uint32_t)__cvta_generic_to_shared(dst);
    int sz = valid ? 16 : 0;
    asm volatile("cp.async.cg.shared.global [%0], [%1], 16, %2;"
                 :: "r"(d), "l"(src), "r"(sz));
}
__device__ __forceinline__ void split_f32(float v, __half& hi, __half& lo) {
    hi = __float2half(v);
    lo = __float2half((v - __half2float(hi)) * LO_SCALE);
}

// ---------------------------------------------------------------------------
// One-time conversions
// ---------------------------------------------------------------------------
// x fp32 -> hi/lo half planes
__global__ void xsplit_k(const float* __restrict__ x)
{
    size_t i = ((size_t)blockIdx.x * 256 + threadIdx.x) * 4;
    float4 v = *(const float4*)(x + i);
    __half h0, l0, h1, l1, h2, l2, h3, l3;
    split_f32(v.x, h0, l0); split_f32(v.y, h1, l1);
    split_f32(v.z, h2, l2); split_f32(v.w, h3, l3);
    *(__half2*)&g_xhi[i]     = __halves2half2(h0, h1);
    *(__half2*)&g_xhi[i + 2] = __halves2half2(h2, h3);
    *(__half2*)&g_xlo[i]     = __halves2half2(l0, l1);
    *(__half2*)&g_xlo[i + 2] = __halves2half2(l2, l3);
}

// W[K][N] fp32 -> Wt[N][K] hi/lo half (transposed split)
__global__ void wsplit_k(const float* __restrict__ W,
                         __half* __restrict__ Whi, __half* __restrict__ Wlo,
                         int K, int N)
{
    __shared__ float t[32][33];
    int k0 = blockIdx.y * 32;
    int n0 = blockIdx.x * 32;
#pragma unroll
    for (int j = 0; j < 4; j++)
        t[threadIdx.y + j * 8][threadIdx.x] =
            W[(size_t)(k0 + threadIdx.y + j * 8) * N + n0 + threadIdx.x];
    __syncthreads();
#pragma unroll
    for (int j = 0; j < 4; j++) {
        int n = n0 + threadIdx.y + j * 8;
        int k = k0 + threadIdx.x;
        float val = t[threadIdx.x][threadIdx.y + j * 8];
        __half hi, lo;
        split_f32(val, hi, lo);
        Whi[(size_t)n * K + k] = hi;
        Wlo[(size_t)n * K + k] = lo;
    }
}

// Expert weights: W[K][N] fp32 -> Wt[N][K] half (single fp16, R7-proven)
__global__ void wconv_k(const float* __restrict__ Wg, __half* __restrict__ Wtg,
                        int K, int N)
{
    const float* W  = Wg  + (size_t)blockIdx.z * K * N;
    __half*      Wt = Wtg + (size_t)blockIdx.z * N * K;
    __shared__ float t[32][33];
    int k0 = blockIdx.y * 32;
    int n0 = blockIdx.x * 32;
#pragma unroll
    for (int j = 0; j < 4; j++) {
        int n = n0 + threadIdx.x;
        if (n < N) t[threadIdx.y + j * 8][threadIdx.x] =
            W[(size_t)(k0 + threadIdx.y + j * 8) * N + n];
    }
    __syncthreads();
#pragma unroll
    for (int j = 0; j < 4; j++) {
        int n = n0 + threadIdx.y + j * 8;
        int k = k0 + threadIdx.x;
        if (n < N) Wt[(size_t)n * K + k] =
            __float2half(t[threadIdx.x][threadIdx.y + j * 8]);
    }
}

// ---------------------------------------------------------------------------
// fp16 2-term-split GEMM for routing stages (fp32-grade, ~22-bit operands):
//   product = Ahi*Bhi  +  (Ahi*Blo' + Alo'*Bhi)/4096    (lo' = 4096*lo)
//   STAGE 0: xsplit @ fw1 -> g_hhi/lo (relu)
//   STAGE 1: g_h    @ fw2 -> g_featshi/lo
//   STAGE 2: feats  @ kw  -> g_pk (fp32)
// Tile 128x128x32, NBUF=2, 8 warps (warp tile 64x32), mma.m16n8k16.
// M=8192, N%128==0, K%32==0 -> no bounds checks.
// ---------------------------------------------------------------------------
#define SBK 32

template<int STAGE, bool RELU>
__global__ __launch_bounds__(256) void sgemm_k(const __half* __restrict__ Whi,
                                               const __half* __restrict__ Wlo,
                                               const float* __restrict__ Bias,
                                               int N, int Kd)
{
    extern __shared__ __half sms[];
    // planes: 0=Ahi 1=Alo 2=Bhi 3=Blo, each [2 buf][128][40]
    __half (*S)[2][128][40] = (__half(*)[2][128][40])sms;

    const __half *Ahi, *Alo;
    if (STAGE == 0)      { Ahi = g_xhi;     Alo = g_xlo;     }
    else if (STAGE == 1) { Ahi = g_hhi;     Alo = g_hlo;     }
    else                 { Ahi = g_featshi; Alo = g_featslo; }

    const int tileM = blockIdx.y * 128;
    const int tileN = blockIdx.x * 128;

    const int tid  = threadIdx.x;
    const int lane = tid & 31;
    const int wid  = tid >> 5;
    const int g    = lane >> 2;
    const int tig  = lane & 3;
    const int warpM = wid & 1;
    const int warpN = wid >> 1;

    const int rr = tid >> 2;        // 0..63
    const int cc = (tid & 3) * 8;   // 0,8,16,24

    const size_t aoff = (size_t)(tileM + rr) * Kd + cc;
    const size_t boff = (size_t)(tileN + rr) * Kd + cc;
    const size_t rstep = (size_t)64 * Kd;

    float acc [4][4][4];
    float accx[4][4][4];
#pragma unroll
    for (int i = 0; i < 4; i++)
#pragma unroll
        for (int j = 0; j < 4; j++)
#pragma unroll
            for (int r = 0; r < 4; r++) { acc[i][j][r] = 0.f; accx[i][j][r] = 0.f; }

    const int KT = Kd / SBK;

    auto load_tile = [&](int k0, int buf) {
#pragma unroll
        for (int it = 0; it < 2; it++) {
            cp16(&S[0][buf][rr + it * 64][cc], Ahi + aoff + it * rstep + k0, true);
            cp16(&S[1][buf][rr + it * 64][cc], Alo + aoff + it * rstep + k0, true);
            cp16(&S[2][buf][rr + it * 64][cc], Whi + boff + it * rstep + k0, true);
            cp16(&S[3][buf][rr + it * 64][cc], Wlo + boff + it * rstep + k0, true);
        }
        asm volatile("cp.async.commit_group;");
    };

    load_tile(0, 0);

    for (int kt = 0; kt < KT; kt++) {
        const int buf = kt & 1;
        if (kt + 1 < KT) {
            load_tile((kt + 1) * SBK, (kt + 1) & 1);
            asm volatile("cp.async.wait_group 1;");
        } else {
            asm volatile("cp.async.wait_group 0;");
        }
        __syncthreads();

#pragma unroll
        for (int ks = 0; ks < 2; ks++) {
            const int k16 = ks * 16;
            uint32_t bh[4][2], bl[4][2];
#pragma unroll
            for (int nf = 0; nf < 4; nf++) {
                int n = warpN * 32 + nf * 8 + g;
                bh[nf][0] = *(const uint32_t*)&S[2][buf][n][k16 + 2 * tig    ];
                bh[nf][1] = *(const uint32_t*)&S[2][buf][n][k16 + 2 * tig + 8];
                bl[nf][0] = *(const uint32_t*)&S[3][buf][n][k16 + 2 * tig    ];
                bl[nf][1] = *(const uint32_t*)&S[3][buf][n][k16 + 2 * tig + 8];
            }
#pragma unroll
            for (int mf = 0; mf < 4; mf++) {
                int m = warpM * 64 + mf * 16 + g;
                uint32_t ah[4], al[4];
                ah[0] = *(const uint32_t*)&S[0][buf][m    ][k16 + 2 * tig    ];
                ah[1] = *(const uint32_t*)&S[0][buf][m + 8][k16 + 2 * tig    ];
                ah[2] = *(const uint32_t*)&S[0][buf][m    ][k16 + 2 * tig + 8];
                ah[3] = *(const uint32_t*)&S[0][buf][m + 8][k16 + 2 * tig + 8];
                al[0] = *(const uint32_t*)&S[1][buf][m    ][k16 + 2 * tig    ];
                al[1] = *(const uint32_t*)&S[1][buf][m + 8][k16 + 2 * tig    ];
                al[2] = *(const uint32_t*)&S[1][buf][m    ][k16 + 2 * tig + 8];
                al[3] = *(const uint32_t*)&S[1][buf][m + 8][k16 + 2 * tig + 8];
#pragma unroll
                for (int nf = 0; nf < 4; nf++) {
                    mma_f16(acc [mf][nf], ah, bh[nf]);
                    mma_f16(accx[mf][nf], ah, bl[nf]);
                    mma_f16(accx[mf][nf], al, bh[nf]);
                }
            }
        }
        __syncthreads();
    }

    // --- epilogue: recombine, bias (+relu), emit split (or fp32) ---
#pragma unroll
    for (int mf = 0; mf < 4; mf++) {
        int row0 = tileM + warpM * 64 + mf * 16 + g;
        int row1 = row0 + 8;
#pragma unroll
        for (int nf = 0; nf < 4; nf++) {
            int col0 = tileN + warpN * 32 + nf * 8 + tig * 2;
            int col1 = col0 + 1;
            float b0 = Bias[col0];
            float b1 = Bias[col1];
            float v00 = acc[mf][nf][0] + accx[mf][nf][0] * LO_INV + b0;
            float v01 = acc[mf][nf][1] + accx[mf][nf][1] * LO_INV + b1;
            float v10 = acc[mf][nf][2] + accx[mf][nf][2] * LO_INV + b0;
            float v11 = acc[mf][nf][3] + accx[mf][nf][3] * LO_INV + b1;
            if (RELU) {
                v00 = fmaxf(v00, 0.f); v01 = fmaxf(v01, 0.f);
                v10 = fmaxf(v10, 0.f); v11 = fmaxf(v11, 0.f);
            }
            if (STAGE == 2) {
                g_pk[(size_t)row0 * N + col0] = v00;
                g_pk[(size_t)row0 * N + col1] = v01;
                g_pk[(size_t)row1 * N + col0] = v10;
                g_pk[(size_t)row1 * N + col1] = v11;
            } else {
                __half* Hi = (STAGE == 0) ? g_hhi : g_featshi;
                __half* Lo = (STAGE == 0) ? g_hlo : g_featslo;
                __half h, l;
                split_f32(v00, h, l);
                Hi[(size_t)row0 * N + col0] = h; Lo[(size_t)row0 * N + col0] = l;
                split_f32(v01, h, l);
                Hi[(size_t)row0 * N + col1] = h; Lo[(size_t)row0 * N + col1] = l;
                split_f32(v10, h, l);
                Hi[(size_t)row1 * N + col0] = h; Lo[(size_t)row1 * N + col0] = l;
                split_f32(v11, h, l);
                Hi[(size_t)row1 * N + col1] = h; Lo[(size_t)row1 * N + col1] = l;
            }
        }
    }
}

// ---------------------------------------------------------------------------
// Pure fp16 expert GEMM (R7-proven). A half k-major, B transposed half [N][K].
// Tile 128x128x64, NBUF=2, 8 warps, mma.m16n8k16.
//   STAGE 3: gather(g_featshi)@ew1h[e] -> g_h1h (relu)
//   STAGE 4: g_h1h@ew2h[e] -> g_h2h (relu)
//   STAGE 5: g_h2h@ew3h[e] -> g_eout (fp32)
// ---------------------------------------------------------------------------
#define HBK 64

template<int STAGE, bool RELU>
__global__ __launch_bounds__(256) void hgemm_k(const __half* __restrict__ Wt,
                                               const float* __restrict__ Biasg,
                                               int N, int Kd)
{
    extern __shared__ __half smh[];
    __half (*Ah)[128][72] = (__half(*)[128][72])smh;
    __half (*Bh)[128][72] = (__half(*)[128][72])(smh + 2 * 128 * 72);

    const int e  = blockIdx.z;
    const int m0 = g_offsets[e];
    const int M  = g_offsets[e + 1] - m0;

    const int tileM = blockIdx.y * 128;
    if (tileM >= M) return;
    const int tileN = blockIdx.x * 128;

    const __half* B = Wt + (size_t)e * N * Kd;
    const float* Bias = Biasg + (size_t)e * N;

    const __half* A;
    __half* Ch = nullptr;
    float*  Cf = nullptr;
    const int* gather = nullptr;
    if (STAGE == 3)      { A = g_featshi; gather = g_list + m0; Ch = g_h1h + (size_t)m0 * N; }
    else if (STAGE == 4) { A = g_h1h + (size_t)m0 * Kd;         Ch = g_h2h + (size_t)m0 * N; }
    else                 { A = g_h2h + (size_t)m0 * Kd;         Cf = g_eout + (size_t)m0 * N; }

    const int tid  = threadIdx.x;
    const int lane = tid & 31;
    const int wid  = tid >> 5;
    const int g    = lane >> 2;
    const int tig  = lane & 3;
    const int warpM = wid & 1;
    const int warpN = wid >> 1;

    const __half* aptr[4];
    bool av[4];
#pragma unroll
    for (int it = 0; it < 4; it++) {
        int r = (tid >> 3) + it * 32;
        int grow = tileM + r;
        av[it] = (grow < M);
        size_t arow = 0;
        if (av[it]) arow = (STAGE == 3) ? (size_t)gather[grow] : (size_t)grow;
        aptr[it] = A + arow * Kd + (tid & 7) * 8;
    }
    const __half* bptr[4];
    bool bvv[4];
#pragma unroll
    for (int it = 0; it < 4; it++) {
        int r = (tid >> 3) + it * 32;
        int gn = tileN + r;
        bvv[it] = (gn < N);
        bptr[it] = B + (size_t)(bvv[it] ? gn : 0) * Kd + (tid & 7) * 8;
    }

    float acc[4][4][4];
#pragma unroll
    for (int i = 0; i < 4; i++)
#pragma unroll
        for (int j = 0; j < 4; j++)
#pragma unroll
            for (int r = 0; r < 4; r++) acc[i][j][r] = 0.f;

    const int KT = Kd / HBK;

    auto load_tile = [&](int k0, int buf) {
#pragma unroll
        for (int it = 0; it < 4; it++) {
            int r = (tid >> 3) + it * 32;
            cp16(&Ah[buf][r][(tid & 7) * 8], aptr[it] + k0, av[it]);
        }
#pragma unroll
        for (int it = 0; it < 4; it++) {
            int r = (tid >> 3) + it * 32;
            cp16(&Bh[buf][r][(tid & 7) * 8], bptr[it] + k0, bvv[it]);
        }
        asm volatile("cp.async.commit_group;");
    };

    load_tile(0, 0);

    for (int kt = 0; kt < KT; kt++) {
        const int buf = kt & 1;
        if (kt + 1 < KT) {
            load_tile((kt + 1) * HBK, (kt + 1) & 1);
            asm volatile("cp.async.wait_group 1;");
        } else {
            asm volatile("cp.async.wait_group 0;");
        }
        __syncthreads();

#pragma unroll
        for (int ks = 0; ks < 4; ks++) {
            const int k16 = ks * 16;
            uint32_t bf[4][2];
#pragma unroll
            for (int nf = 0; nf < 4; nf++) {
                int n = warpN * 32 + nf * 8 + g;
                bf[nf][0] = *(const uint32_t*)&Bh[buf][n][k16 + 2 * tig    ];
                bf[nf][1] = *(const uint32_t*)&Bh[buf][n][k16 + 2 * tig + 8];
            }
#pragma unroll
            for (int mf = 0; mf < 4; mf++) {
                int m = warpM * 64 + mf * 16 + g;
                uint32_t af[4];
                af[0] = *(const uint32_t*)&Ah[buf][m    ][k16 + 2 * tig    ];
                af[1] = *(const uint32_t*)&Ah[buf][m + 8][k16 + 2 * tig    ];
                af[2] = *(const uint32_t*)&Ah[buf][m    ][k16 + 2 * tig + 8];
                af[3] = *(const uint32_t*)&Ah[buf][m + 8][k16 + 2 * tig + 8];
#pragma unroll
                for (int nf = 0; nf < 4; nf++)
                    mma_f16(acc[mf][nf], af, bf[nf]);
            }
        }
        __syncthreads();
    }

#pragma unroll
    for (int mf = 0; mf < 4; mf++) {
        int row0 = tileM + warpM * 64 + mf * 16 + g;
        int row1 = row0 + 8;
#pragma unroll
        for (int nf = 0; nf < 4; nf++) {
            int col0 = tileN + warpN * 32 + nf * 8 + tig * 2;
            int col1 = col0 + 1;
            float b0 = (col0 < N) ? Bias[col0] : 0.f;
            float b1 = (col1 < N) ? Bias[col1] : 0.f;
            float v00 = acc[mf][nf][0] + b0;
            float v01 = acc[mf][nf][1] + b1;
            float v10 = acc[mf][nf][2] + b0;
            float v11 = acc[mf][nf][3] + b1;
            if (RELU) {
                v00 = fmaxf(v00, 0.f); v01 = fmaxf(v01, 0.f);
                v10 = fmaxf(v10, 0.f); v11 = fmaxf(v11, 0.f);
            }
            if (STAGE == 5) {
                if (row0 < M) {
                    if (col0 < N) Cf[(size_t)row0 * N + col0] = v00;
                    if (col1 < N) Cf[(size_t)row0 * N + col1] = v01;
                }
                if (row1 < M) {
                    if (col0 < N) Cf[(size_t)row1 * N + col0] = v10;
                    if (col1 < N) Cf[(size_t)row1 * N + col1] = v11;
                }
            } else {
                if (row0 < M) {
                    if (col0 < N) Ch[(size_t)row0 * N + col0] = __float2half(v00);
                    if (col1 < N) Ch[(size_t)row0 * N + col1] = __float2half(v01);
                }
                if (row1 < M) {
                    if (col0 < N) Ch[(size_t)row1 * N + col0] = __float2half(v10);
                    if (col1 < N) Ch[(size_t)row1 * N + col1] = __float2half(v11);
                }
            }
        }
    }
}

// ---------------------------------------------------------------------------
// keys normalization / routing / grouping / combine
// ---------------------------------------------------------------------------
__global__ void keysn_kernel(const float* __restrict__ keys)
{
    int e    = threadIdx.x >> 5;
    int lane = threadIdx.x & 31;
    if (e >= EDIM) return;
    float4 v = *(const float4*)(keys + e * KDIM + lane * 4);
    float ss = v.x * v.x + v.y * v.y + v.z * v.z + v.w * v.w;
#pragma unroll
    for (int o = 16; o; o >>= 1) ss += __shfl_xor_sync(0xffffffffu, ss, o);
    float inv = 1.f / fmaxf(sqrtf(ss), 1e-12f);
    float4 o4 = make_float4(v.x * inv, v.y * inv, v.z * inv, v.w * inv);
    *(float4*)(g_keysn + e * KDIM + lane * 4) = o4;
}

__global__ void zero_counts_kernel()
{
    if (threadIdx.x < EDIM) g_counts[threadIdx.x] = 0;
}

__global__ void router_kernel()
{
    int warp = threadIdx.x >> 5;
    int lane = threadIdx.x & 31;
    int t = blockIdx.x * 8 + warp;
    if (t >= BDIM) return;

    float4 v = *(const float4*)(g_pk + (size_t)t * KDIM + lane * 4);
    float ss = v.x * v.x + v.y * v.y + v.z * v.z + v.w * v.w;
#pragma unroll
    for (int o = 16; o; o >>= 1) ss += __shfl_xor_sync(0xffffffffu, ss, o);
    float inv = 1.f / fmaxf(sqrtf(ss), 1e-12f);

    float sims[EDIM];
#pragma unroll
    for (int e = 0; e < EDIM; e++) {
        float4 kv = *(const float4*)(g_keysn + e * KDIM + lane * 4);
        float d = v.x * kv.x + v.y * kv.y + v.z * kv.z + v.w * kv.w;
#pragma unroll
        for (int o = 16; o; o >>= 1) d += __shfl_xor_sync(0xffffffffu, d, o);
        sims[e] = d * inv;
    }

    if (lane == 0) {
        int i0 = 0; float v0 = sims[0];
#pragma unroll
        for (int e = 1; e < EDIM; e++) if (sims[e] > v0) { v0 = sims[e]; i0 = e; }
        int i1 = -1; float v1 = -1e30f;
#pragma unroll
        for (int e = 0; e < EDIM; e++) if (e != i0 && sims[e] > v1) { v1 = sims[e]; i1 = e; }

        float e1 = expf(v1 - v0);
        float s  = 1.f + e1;
        float w0 = 1.f / s;
        float w1 = e1 / s;

#pragma unroll
        for (int e = 0; e < EDIM; e++) {
            g_sim[t * EDIM + e] = sims[e];
            g_weights[t * EDIM + e] = (e == i0) ? w0 : ((e == i1) ? w1 : 0.f);
        }
        g_topi[t * TOPK + 0] = i0;
        g_topi[t * TOPK + 1] = i1;
        g_wslot[t * TOPK + 0] = w0;
        g_wslot[t * TOPK + 1] = w1;
        atomicAdd(&g_counts[i0], 1);
        atomicAdd(&g_counts[i1], 1);
    }
}

__global__ void scan_kernel()
{
    if (threadIdx.x == 0) {
        int off = 0;
        for (int e = 0; e < EDIM; e++) {
            g_offsets[e] = off;
            g_cursor[e]  = off;
            off += g_counts[e];
        }
        g_offsets[EDIM] = off;
    }
}

__global__ void scatter_kernel()
{
    int t = blockIdx.x * blockDim.x + threadIdx.x;
    if (t >= BDIM) return;
#pragma unroll
    for (int s = 0; s < TOPK; s++) {
        int e = g_topi[t * TOPK + s];
        int pos = atomicAdd(&g_cursor[e], 1);
        g_list[pos] = t;
        g_pos[t * TOPK + s] = pos;
    }
}

__global__ void combine_kernel(float* __restrict__ out)
{
    int t = blockIdx.x;
    float w0 = g_wslot[t * TOPK + 0];
    float w1 = g_wslot[t * TOPK + 1];
    size_t p0 = (size_t)g_pos[t * TOPK + 0];
    size_t p1 = (size_t)g_pos[t * TOPK + 1];
    for (int c = threadIdx.x; c < CDIM; c += blockDim.x)
        out[(size_t)t * CDIM + c] =
            w0 * g_eout[p0 * CDIM + c] + w1 * g_eout[p1 * CDIM + c];
}

__global__ void tail_writer_kernel(float* __restrict__ out, long long out_size)
{
    long long i = (long long)blockIdx.x * blockDim.x + threadIdx.x;
    const long long base_w = (long long)BDIM * CDIM;
    const long long n_w = BDIM * EDIM;
    const long long base_t = base_w + n_w;
    const long long n_t = BDIM * TOPK;
    const long long base_s = base_t + n_t;
    const long long n_s = BDIM * EDIM;
    if (i < n_w && base_w + i < out_size) out[base_w + i] = g_weights[i];
    if (i < n_t && base_t + i < out_size) out[base_t + i] = (float)g_topi[i];
    if (i < n_s && base_s + i < out_size) out[base_s + i] = g_sim[i];
}

// ---------------------------------------------------------------------------
// Launch
// ---------------------------------------------------------------------------
#define SG_SMEM (4 * 2 * 128 * 40 * (int)sizeof(__half))   // 81920 B
#define HG_SMEM (2 * 2 * 128 * 72 * (int)sizeof(__half))   // 73728 B

extern "C" void kernel_launch(void* const* d_in, const int* in_sizes, int n_in,
                              void* d_out, int out_size)
{
    const float* x    = (const float*)d_in[0];
    const float* fw1  = (const float*)d_in[1];
    const float* fb1  = (const float*)d_in[2];
    const float* fw2  = (const float*)d_in[3];
    const float* fb2  = (const float*)d_in[4];
    const float* kw   = (const float*)d_in[5];
    const float* kb   = (const float*)d_in[6];
    const float* keys = (const float*)d_in[7];
    const float* ew1  = (const float*)d_in[8];
    const float* eb1  = (const float*)d_in[9];
    const float* ew2  = (const float*)d_in[10];
    const float* eb2  = (const float*)d_in[11];
    const float* ew3  = (const float*)d_in[12];
    const float* eb3  = (const float*)d_in[13];
    float* out = (float*)d_out;

    cudaFuncSetAttribute(sgemm_k<0, true >, cudaFuncAttributeMaxDynamicSharedMemorySize, SG_SMEM);
    cudaFuncSetAttribute(sgemm_k<1, false>, cudaFuncAttributeMaxDynamicSharedMemorySize, SG_SMEM);
    cudaFuncSetAttribute(sgemm_k<2, false>, cudaFuncAttributeMaxDynamicSharedMemorySize, SG_SMEM);
    cudaFuncSetAttribute(hgemm_k<3, true >, cudaFuncAttributeMaxDynamicSharedMemorySize, HG_SMEM);
    cudaFuncSetAttribute(hgemm_k<4, true >, cudaFuncAttributeMaxDynamicSharedMemorySize, HG_SMEM);
    cudaFuncSetAttribute(hgemm_k<5, false>, cudaFuncAttributeMaxDynamicSharedMemorySize, HG_SMEM);

    dim3 blk(256);
    dim3 tblk(32, 8);

    // symbol addresses for converted weights
    __half *fw1hi, *fw1lo, *fw2hi, *fw2lo, *kwhi, *kwlo, *ew1h, *ew2h, *ew3h;
    cudaGetSymbolAddress((void**)&fw1hi, g_fw1hi);
    cudaGetSymbolAddress((void**)&fw1lo, g_fw1lo);
    cudaGetSymbolAddress((void**)&fw2hi, g_fw2hi);
    cudaGetSymbolAddress((void**)&fw2lo, g_fw2lo);
    cudaGetSymbolAddress((void**)&kwhi,  g_kwhi);
    cudaGetSymbolAddress((void**)&kwlo,  g_kwlo);
    cudaGetSymbolAddress((void**)&ew1h,  g_ew1h);
    cudaGetSymbolAddress((void**)&ew2h,  g_ew2h);
    cudaGetSymbolAddress((void**)&ew3h,  g_ew3h);

    // one-time conversions
    xsplit_k<<<BDIM * DDIM / 4 / 256, 256>>>(x);
    wsplit_k<<<dim3(HDIM / 32, DDIM / 32), tblk>>>(fw1, fw1hi, fw1lo, DDIM, HDIM);
    wsplit_k<<<dim3(HDIM / 32, HDIM / 32), tblk>>>(fw2, fw2hi, fw2lo, HDIM, HDIM);
    wsplit_k<<<dim3(KDIM / 32, HDIM / 32), tblk>>>(kw,  kwhi,  kwlo,  HDIM, KDIM);
    wconv_k<<<dim3(HDIM / 32,        HDIM / 32,  EDIM), tblk>>>(ew1, ew1h, HDIM,  HDIM);
    wconv_k<<<dim3(H2DIM / 32,       HDIM / 32,  EDIM), tblk>>>(ew2, ew2h, HDIM,  H2DIM);
    wconv_k<<<dim3((CDIM + 31) / 32, H2DIM / 32, EDIM), tblk>>>(ew3, ew3h, H2DIM, CDIM);

    keysn_kernel<<<1, 256>>>(keys);
    zero_counts_kernel<<<1, 32>>>();

    // feature extractor + router projection: fp16 2-term split (fp32-grade)
    sgemm_k<0, true ><<<dim3(HDIM / 128, BDIM / 128), blk, SG_SMEM>>>(fw1hi, fw1lo, fb1, HDIM, DDIM);
    sgemm_k<1, false><<<dim3(HDIM / 128, BDIM / 128), blk, SG_SMEM>>>(fw2hi, fw2lo, fb2, HDIM, HDIM);
    sgemm_k<2, false><<<dim3(KDIM / 128, BDIM / 128), blk, SG_SMEM>>>(kwhi,  kwlo,  kb,  KDIM, HDIM);

    router_kernel<<<BDIM / 8, 256>>>();
    scan_kernel<<<1, 32>>>();
    scatter_kernel<<<(BDIM + 255) / 256, 256>>>();

    // expert MLPs: pure fp16 tensor-core GEMMs on grouped rows
    hgemm_k<3, true ><<<dim3(HDIM / 128,         BDIM / 128, EDIM), blk, HG_SMEM>>>(ew1h, eb1, HDIM,  HDIM);
    hgemm_k<4, true ><<<dim3(H2DIM / 128,        BDIM / 128, EDIM), blk, HG_SMEM>>>(ew2h, eb2, H2DIM, HDIM);
    hgemm_k<5, false><<<dim3((CDIM + 127) / 128, BDIM / 128, EDIM), blk, HG_SMEM>>>(ew3h, eb3, CDIM,  H2DIM);

    combine_kernel<<<BDIM, 256>>>(out);
    tail_writer_kernel<<<(BDIM * EDIM + 255) / 256, 256>>>(out, (long long)out_size);
}

// round 10
// speedup vs baseline: 1.9969x; 1.1502x over previous
#include <cuda_runtime.h>
#include <cuda_fp16.h>
#include <math.h>
#include <stdint.h>

// ---------------------------------------------------------------------------
// Problem constants
// ---------------------------------------------------------------------------
#define BDIM   8192
#define DDIM   1024
#define HDIM   2048
#define H2DIM  1024
#define CDIM   1000
#define KDIM   128
#define EDIM   8
#define TOPK   2
#define MAXROWS (BDIM * TOPK)

// ---------------------------------------------------------------------------
// Scratch (device globals — no allocation allowed)
// ---------------------------------------------------------------------------
__device__ __half g_xhi  [(size_t)BDIM * DDIM];
__device__ __half g_xlo  [(size_t)BDIM * DDIM];
__device__ __half g_hhi  [(size_t)BDIM * HDIM];
__device__ __half g_hlo  [(size_t)BDIM * HDIM];
__device__ __half g_featshi[(size_t)BDIM * HDIM];
__device__ float  g_pk   [(size_t)BDIM * KDIM];
__device__ float  g_keysn[EDIM * KDIM];
__device__ float  g_sim  [BDIM * EDIM];
__device__ float  g_weights[BDIM * EDIM];
__device__ float  g_wslot[BDIM * TOPK];
__device__ int    g_topi [BDIM * TOPK];
__device__ int    g_counts[EDIM];
__device__ int    g_offsets[EDIM + 1];
__device__ int    g_cursor[EDIM];
__device__ int    g_list [MAXROWS];
__device__ int    g_pos  [BDIM * TOPK];
__device__ __half g_h1h  [(size_t)MAXROWS * HDIM];
__device__ __half g_h2h  [(size_t)MAXROWS * H2DIM];
__device__ float  g_eout [(size_t)MAXROWS * CDIM];
// converted weights
__device__ __half g_fw1hi[(size_t)HDIM * DDIM];   // fw1^T split  [H][D]
__device__ __half g_fw1lo[(size_t)HDIM * DDIM];
__device__ __half g_fw2h [(size_t)HDIM * HDIM];   // fw2^T single [Hout][Hin]
__device__ __half g_fw2nhi[(size_t)HDIM * HDIM];  // fw2 natural split [Hin][Hout]
__device__ __half g_fw2nlo[(size_t)HDIM * HDIM];
__device__ __half g_kwhi [(size_t)KDIM * HDIM];   // kw^T split   [K][H]
__device__ __half g_kwlo [(size_t)KDIM * HDIM];
__device__ __half g_wphi [(size_t)KDIM * HDIM];   // W'^T split   [K][H]
__device__ __half g_wplo [(size_t)KDIM * HDIM];
__device__ float  g_bp   [KDIM];                  // b' = fb2@kw + kb
__device__ float  g_zbias[HDIM];                  // zeros (static init)
__device__ __half g_ew1h [(size_t)EDIM * HDIM  * HDIM];
__device__ __half g_ew2h [(size_t)EDIM * H2DIM * HDIM];
__device__ __half g_ew3h [(size_t)EDIM * CDIM  * H2DIM];

#define LO_SCALE 4096.0f
#define LO_INV   (1.0f / 4096.0f)

// ---------------------------------------------------------------------------
// helpers
// ---------------------------------------------------------------------------
__device__ __forceinline__ void mma_f16(float c[4],
                                        const uint32_t a[4],
                                        const uint32_t b[2]) {
    asm volatile(
        "mma.sync.aligned.m16n8k16.row.col.f32.f16.f16.f32 "
        "{%0,%1,%2,%3}, {%4,%5,%6,%7}, {%8,%9}, {%0,%1,%2,%3};"
        : "+f"(c[0]), "+f"(c[1]), "+f"(c[2]), "+f"(c[3])
        : "r"(a[0]), "r"(a[1]), "r"(a[2]), "r"(a[3]),
          "r"(b[0]), "r"(b[1]));
}
__device__ __forceinline__ void cp16(void* dst, const void* src, bool valid) {
    uint32_t d = (uint32_t)__cvta_generic_to_shared(dst);
    int sz = valid ? 16 : 0;
    asm volatile("cp.async.cg.shared.global [%0], [%1], 16, %2;"
                 :: "r"(d), "l"(src), "r"(sz));
}
__device__ __forceinline__ void split_f32(float v, __half& hi, __half& lo) {
    hi = __float2half(v);
    lo = __float2half((v - __half2float(hi)) * LO_SCALE);
}

// ---------------------------------------------------------------------------
// One-time conversions
// ---------------------------------------------------------------------------
// elementwise fp32 -> hi/lo split (natural layout)
__global__ void natsplit_k(const float* __restrict__ W,
                           __half* __restrict__ Whi, __half* __restrict__ Wlo)
{
    size_t i = ((size_t)blockIdx.x * 256 + threadIdx.x) * 4;
    float4 v = *(const float4*)(W + i);
    __half h0, l0, h1, l1, h2, l2, h3, l3;
    split_f32(v.x, h0, l0); split_f32(v.y, h1, l1);
    split_f32(v.z, h2, l2); split_f32(v.w, h3, l3);
    *(__half2*)&Whi[i]     = __halves2half2(h0, h1);
    *(__half2*)&Whi[i + 2] = __halves2half2(h2, h3);
    *(__half2*)&Wlo[i]     = __halves2half2(l0, l1);
    *(__half2*)&Wlo[i + 2] = __halves2half2(l2, l3);
}

// W[K][N] fp32 -> Wt[N][K] hi/lo half (transposed split)
__global__ void wsplit_k(const float* __restrict__ W,
                         __half* __restrict__ Whi, __half* __restrict__ Wlo,
                         int K, int N)
{
    __shared__ float t[32][33];
    int k0 = blockIdx.y * 32;
    int n0 = blockIdx.x * 32;
#pragma unroll
    for (int j = 0; j < 4; j++)
        t[threadIdx.y + j * 8][threadIdx.x] =
            W[(size_t)(k0 + threadIdx.y + j * 8) * N + n0 + threadIdx.x];
    __syncthreads();
#pragma unroll
    for (int j = 0; j < 4; j++) {
        int n = n0 + threadIdx.y + j * 8;
        int k = k0 + threadIdx.x;
        float val = t[threadIdx.x][threadIdx.y + j * 8];
        __half hi, lo;
        split_f32(val, hi, lo);
        Whi[(size_t)n * K + k] = hi;
        Wlo[(size_t)n * K + k] = lo;
    }
}

// W[K][N] fp32 -> Wt[N][K] half (transposed single fp16; per-expert via z)
__global__ void wconv_k(const float* __restrict__ Wg, __half* __restrict__ Wtg,
                        int K, int N)
{
    const float* W  = Wg  + (size_t)blockIdx.z * K * N;
    __half*      Wt = Wtg + (size_t)blockIdx.z * N * K;
    __shared__ float t[32][33];
    int k0 = blockIdx.y * 32;
    int n0 = blockIdx.x * 32;
#pragma unroll
    for (int j = 0; j < 4; j++) {
        int n = n0 + threadIdx.x;
        if (n < N) t[threadIdx.y + j * 8][threadIdx.x] =
            W[(size_t)(k0 + threadIdx.y + j * 8) * N + n];
    }
    __syncthreads();
#pragma unroll
    for (int j = 0; j < 4; j++) {
        int n = n0 + threadIdx.y + j * 8;
        int k = k0 + threadIdx.x;
        if (n < N) Wt[(size_t)n * K + k] =
            __float2half(t[threadIdx.x][threadIdx.y + j * 8]);
    }
}

// b'[j] = kb[j] + sum_m fb2[m] * kw[m][j]
__global__ void bprime_k(const float* __restrict__ fb2,
                         const float* __restrict__ kw,
                         const float* __restrict__ kb)
{
    int j = blockIdx.x;
    float s = 0.f;
    for (int m = threadIdx.x; m < HDIM; m += 256)
        s += fb2[m] * kw[(size_t)m * KDIM + j];
    __shared__ float red[8];
#pragma unroll
    for (int o = 16; o; o >>= 1) s += __shfl_xor_sync(0xffffffffu, s, o);
    if ((threadIdx.x & 31) == 0) red[threadIdx.x >> 5] = s;
    __syncthreads();
    if (threadIdx.x == 0) {
        float t = 0.f;
#pragma unroll
        for (int w = 0; w < 8; w++) t += red[w];
        g_bp[j] = t + kb[j];
    }
}

// ---------------------------------------------------------------------------
// fp16 2-term-split GEMM (fp32-grade, ~22-bit operands) — R8-proven core.
//   STAGE 0: xsplit @ fw1   -> g_hhi/lo (relu)           M=8192,N=2048,K=1024
//   STAGE 2: hsplit @ W'    -> g_pk (fp32, bias b')      M=8192,N=128, K=2048
//   STAGE 7: kw^T   @ fw2n  -> g_wphi/lo (= W'^T)        M=128, N=2048,K=2048
// Tile 128x128x32, NBUF=2, 8 warps (warp tile 64x32), mma.m16n8k16.
// ---------------------------------------------------------------------------
#define SBK 32

template<int STAGE, bool RELU>
__global__ __launch_bounds__(256) void sgemm_k(const __half* __restrict__ Whi,
                                               const __half* __restrict__ Wlo,
                                               const float* __restrict__ Bias,
                                               int N, int Kd)
{
    extern __shared__ __half sms[];
    __half (*S)[2][128][40] = (__half(*)[2][128][40])sms;

    const __half *Ahi, *Alo;
    if (STAGE == 0)      { Ahi = g_xhi;  Alo = g_xlo;  }
    else if (STAGE == 2) { Ahi = g_hhi;  Alo = g_hlo;  }
    else                 { Ahi = g_kwhi; Alo = g_kwlo; }

    const int tileM = blockIdx.y * 128;
    const int tileN = blockIdx.x * 128;

    const int tid  = threadIdx.x;
    const int lane = tid & 31;
    const int wid  = tid >> 5;
    const int g    = lane >> 2;
    const int tig  = lane & 3;
    const int warpM = wid & 1;
    const int warpN = wid >> 1;

    const int rr = tid >> 2;
    const int cc = (tid & 3) * 8;

    const size_t aoff = (size_t)(tileM + rr) * Kd + cc;
    const size_t boff = (size_t)(tileN + rr) * Kd + cc;
    const size_t rstep = (size_t)64 * Kd;

    float acc [4][4][4];
    float accx[4][4][4];
#pragma unroll
    for (int i = 0; i < 4; i++)
#pragma unroll
        for (int j = 0; j < 4; j++)
#pragma unroll
            for (int r = 0; r < 4; r++) { acc[i][j][r] = 0.f; accx[i][j][r] = 0.f; }

    const int KT = Kd / SBK;

    auto load_tile = [&](int k0, int buf) {
#pragma unroll
        for (int it = 0; it < 2; it++) {
            cp16(&S[0][buf][rr + it * 64][cc], Ahi + aoff + it * rstep + k0, true);
            cp16(&S[1][buf][rr + it * 64][cc], Alo + aoff + it * rstep + k0, true);
            cp16(&S[2][buf][rr + it * 64][cc], Whi + boff + it * rstep + k0, true);
            cp16(&S[3][buf][rr + it * 64][cc], Wlo + boff + it * rstep + k0, true);
        }
        asm volatile("cp.async.commit_group;");
    };

    load_tile(0, 0);

    for (int kt = 0; kt < KT; kt++) {
        const int buf = kt & 1;
        if (kt + 1 < KT) {
            load_tile((kt + 1) * SBK, (kt + 1) & 1);
            asm volatile("cp.async.wait_group 1;");
        } else {
            asm volatile("cp.async.wait_group 0;");
        }
        __syncthreads();

#pragma unroll
        for (int ks = 0; ks < 2; ks++) {
            const int k16 = ks * 16;
            uint32_t bh[4][2], bl[4][2];
#pragma unroll
            for (int nf = 0; nf < 4; nf++) {
                int n = warpN * 32 + nf * 8 + g;
                bh[nf][0] = *(const uint32_t*)&S[2][buf][n][k16 + 2 * tig    ];
                bh[nf][1] = *(const uint32_t*)&S[2][buf][n][k16 + 2 * tig + 8];
                bl[nf][0] = *(const uint32_t*)&S[3][buf][n][k16 + 2 * tig    ];
                bl[nf][1] = *(const uint32_t*)&S[3][buf][n][k16 + 2 * tig + 8];
            }
#pragma unroll
            for (int mf = 0; mf < 4; mf++) {
                int m = warpM * 64 + mf * 16 + g;
                uint32_t ah[4], al[4];
                ah[0] = *(const uint32_t*)&S[0][buf][m    ][k16 + 2 * tig    ];
                ah[1] = *(const uint32_t*)&S[0][buf][m + 8][k16 + 2 * tig    ];
                ah[2] = *(const uint32_t*)&S[0][buf][m    ][k16 + 2 * tig + 8];
                ah[3] = *(const uint32_t*)&S[0][buf][m + 8][k16 + 2 * tig + 8];
                al[0] = *(const uint32_t*)&S[1][buf][m    ][k16 + 2 * tig    ];
                al[1] = *(const uint32_t*)&S[1][buf][m + 8][k16 + 2 * tig    ];
                al[2] = *(const uint32_t*)&S[1][buf][m    ][k16 + 2 * tig + 8];
                al[3] = *(const uint32_t*)&S[1][buf][m + 8][k16 + 2 * tig + 8];
#pragma unroll
                for (int nf = 0; nf < 4; nf++) {
                    mma_f16(acc [mf][nf], ah, bh[nf]);
                    mma_f16(accx[mf][nf], ah, bl[nf]);
                    mma_f16(accx[mf][nf], al, bh[nf]);
                }
            }
        }
        __syncthreads();
    }

#pragma unroll
    for (int mf = 0; mf < 4; mf++) {
        int row0 = tileM + warpM * 64 + mf * 16 + g;
        int row1 = row0 + 8;
#pragma unroll
        for (int nf = 0; nf < 4; nf++) {
            int col0 = tileN + warpN * 32 + nf * 8 + tig * 2;
            int col1 = col0 + 1;
            float b0 = Bias[col0];
            float b1 = Bias[col1];
            float v00 = acc[mf][nf][0] + accx[mf][nf][0] * LO_INV + b0;
            float v01 = acc[mf][nf][1] + accx[mf][nf][1] * LO_INV + b1;
            float v10 = acc[mf][nf][2] + accx[mf][nf][2] * LO_INV + b0;
            float v11 = acc[mf][nf][3] + accx[mf][nf][3] * LO_INV + b1;
            if (RELU) {
                v00 = fmaxf(v00, 0.f); v01 = fmaxf(v01, 0.f);
                v10 = fmaxf(v10, 0.f); v11 = fmaxf(v11, 0.f);
            }
            if (STAGE == 2) {
                g_pk[(size_t)row0 * N + col0] = v00;
                g_pk[(size_t)row0 * N + col1] = v01;
                g_pk[(size_t)row1 * N + col0] = v10;
                g_pk[(size_t)row1 * N + col1] = v11;
            } else {
                __half* Hi = (STAGE == 0) ? g_hhi : g_wphi;
                __half* Lo = (STAGE == 0) ? g_hlo : g_wplo;
                __half h, l;
                split_f32(v00, h, l);
                Hi[(size_t)row0 * N + col0] = h; Lo[(size_t)row0 * N + col0] = l;
                split_f32(v01, h, l);
                Hi[(size_t)row0 * N + col1] = h; Lo[(size_t)row0 * N + col1] = l;
                split_f32(v10, h, l);
                Hi[(size_t)row1 * N + col0] = h; Lo[(size_t)row1 * N + col0] = l;
                split_f32(v11, h, l);
                Hi[(size_t)row1 * N + col1] = h; Lo[(size_t)row1 * N + col1] = l;
            }
        }
    }
}

// ---------------------------------------------------------------------------
// Pure fp16 GEMM (R7-proven). A half k-major, B transposed half [N][K].
// Tile 128x128x64, NBUF=2, 8 warps, mma.m16n8k16.
//   STAGE 1: g_hhi@fw2h -> g_featshi (no relu)          M=BDIM
//   STAGE 3: gather(g_featshi)@ew1h[e] -> g_h1h (relu)  grouped
//   STAGE 4: g_h1h@ew2h[e] -> g_h2h (relu)
//   STAGE 5: g_h2h@ew3h[e] -> g_eout (fp32)
// ---------------------------------------------------------------------------
#define HBK 64

template<int STAGE, bool RELU>
__global__ __launch_bounds__(256) void hgemm_k(const __half* __restrict__ Wt,
                                               const float* __restrict__ Biasg,
                                               int N, int Kd)
{
    extern __shared__ __half smh[];
    __half (*Ah)[128][72] = (__half(*)[128][72])smh;
    __half (*Bh)[128][72] = (__half(*)[128][72])(smh + 2 * 128 * 72);

    int M;
    const __half* B;
    const float* Bias;
    const __half* A;
    __half* Ch = nullptr;
    float*  Cf = nullptr;
    const int* gather = nullptr;

    if (STAGE == 1) {
        M = BDIM; B = Wt; Bias = Biasg;
        A = g_hhi; Ch = g_featshi;
    } else {
        int e  = blockIdx.z;
        int m0 = g_offsets[e];
        M = g_offsets[e + 1] - m0;
        B    = Wt    + (size_t)e * N * Kd;
        Bias = Biasg + (size_t)e * N;
        if (STAGE == 3)      { A = g_featshi; gather = g_list + m0; Ch = g_h1h + (size_t)m0 * N; }
        else if (STAGE == 4) { A = g_h1h + (size_t)m0 * Kd;         Ch = g_h2h + (size_t)m0 * N; }
        else                 { A = g_h2h + (size_t)m0 * Kd;         Cf = g_eout + (size_t)m0 * N; }
    }

    const int tileM = blockIdx.y * 128;
    if (tileM >= M) return;
    const int tileN = blockIdx.x * 128;

    const int tid  = threadIdx.x;
    const int lane = tid & 31;
    const int wid  = tid >> 5;
    const int g    = lane >> 2;
    const int tig  = lane & 3;
    const int warpM = wid & 1;
    const int warpN = wid >> 1;

    const __half* aptr[4];
    bool av[4];
#pragma unroll
    for (int it = 0; it < 4; it++) {
        int r = (tid >> 3) + it * 32;
        int grow = tileM + r;
        av[it] = (grow < M);
        size_t arow = 0;
        if (av[it]) arow = (STAGE == 3) ? (size_t)gather[grow] : (size_t)grow;
        aptr[it] = A + arow * Kd + (tid & 7) * 8;
    }
    const __half* bptr[4];
    bool bvv[4];
#pragma unroll
    for (int it = 0; it < 4; it++) {
        int r = (tid >> 3) + it * 32;
        int gn = tileN + r;
        bvv[it] = (gn < N);
        bptr[it] = B + (size_t)(bvv[it] ? gn : 0) * Kd + (tid & 7) * 8;
    }

    float acc[4][4][4];
#pragma unroll
    for (int i = 0; i < 4; i++)
#pragma unroll
        for (int j = 0; j < 4; j++)
#pragma unroll
            for (int r = 0; r < 4; r++) acc[i][j][r] = 0.f;

    const int KT = Kd / HBK;

    auto load_tile = [&](int k0, int buf) {
#pragma unroll
        for (int it = 0; it < 4; it++) {
            int r = (tid >> 3) + it * 32;
            cp16(&Ah[buf][r][(tid & 7) * 8], aptr[it] + k0, av[it]);
        }
#pragma unroll
        for (int it = 0; it < 4; it++) {
            int r = (tid >> 3) + it * 32;
            cp16(&Bh[buf][r][(tid & 7) * 8], bptr[it] + k0, bvv[it]);
        }
        asm volatile("cp.async.commit_group;");
    };

    load_tile(0, 0);

    for (int kt = 0; kt < KT; kt++) {
        const int buf = kt & 1;
        if (kt + 1 < KT) {
            load_tile((kt + 1) * HBK, (kt + 1) & 1);
            asm volatile("cp.async.wait_group 1;");
        } else {
            asm volatile("cp.async.wait_group 0;");
        }
        __syncthreads();

#pragma unroll
        for (int ks = 0; ks < 4; ks++) {
            const int k16 = ks * 16;
            uint32_t bf[4][2];
#pragma unroll
            for (int nf = 0; nf < 4; nf++) {
                int n = warpN * 32 + nf * 8 + g;
                bf[nf][0] = *(const uint32_t*)&Bh[buf][n][k16 + 2 * tig    ];
                bf[nf][1] = *(const uint32_t*)&Bh[buf][n][k16 + 2 * tig + 8];
            }
#pragma unroll
            for (int mf = 0; mf < 4; mf++) {
                int m = warpM * 64 + mf * 16 + g;
                uint32_t af[4];
                af[0] = *(const uint32_t*)&Ah[buf][m    ][k16 + 2 * tig    ];
                af[1] = *(const uint32_t*)&Ah[buf][m + 8][k16 + 2 * tig    ];
                af[2] = *(const uint32_t*)&Ah[buf][m    ][k16 + 2 * tig + 8];
                af[3] = *(const uint32_t*)&Ah[buf][m + 8][k16 + 2 * tig + 8];
#pragma unroll
                for (int nf = 0; nf < 4; nf++)
                    mma_f16(acc[mf][nf], af, bf[nf]);
            }
        }
        __syncthreads();
    }

#pragma unroll
    for (int mf = 0; mf < 4; mf++) {
        int row0 = tileM + warpM * 64 + mf * 16 + g;
        int row1 = row0 + 8;
#pragma unroll
        for (int nf = 0; nf < 4; nf++) {
            int col0 = tileN + warpN * 32 + nf * 8 + tig * 2;
            int col1 = col0 + 1;
            float b0 = (col0 < N) ? Bias[col0] : 0.f;
            float b1 = (col1 < N) ? Bias[col1] : 0.f;
            float v00 = acc[mf][nf][0] + b0;
            float v01 = acc[mf][nf][1] + b1;
            float v10 = acc[mf][nf][2] + b0;
            float v11 = acc[mf][nf][3] + b1;
            if (RELU) {
                v00 = fmaxf(v00, 0.f); v01 = fmaxf(v01, 0.f);
                v10 = fmaxf(v10, 0.f); v11 = fmaxf(v11, 0.f);
            }
            if (STAGE == 5) {
                if (row0 < M) {
                    if (col0 < N) Cf[(size_t)row0 * N + col0] = v00;
                    if (col1 < N) Cf[(size_t)row0 * N + col1] = v01;
                }
                if (row1 < M) {
                    if (col0 < N) Cf[(size_t)row1 * N + col0] = v10;
                    if (col1 < N) Cf[(size_t)row1 * N + col1] = v11;
                }
            } else {
                if (row0 < M) {
                    if (col0 < N) Ch[(size_t)row0 * N + col0] = __float2half(v00);
                    if (col1 < N) Ch[(size_t)row0 * N + col1] = __float2half(v01);
                }
                if (row1 < M) {
                    if (col0 < N) Ch[(size_t)row1 * N + col0] = __float2half(v10);
                    if (col1 < N) Ch[(size_t)row1 * N + col1] = __float2half(v11);
                }
            }
        }
    }
}

// ---------------------------------------------------------------------------
// keys normalization / routing / grouping / combine
// ---------------------------------------------------------------------------
__global__ void keysn_kernel(const float* __restrict__ keys)
{
    int e    = threadIdx.x >> 5;
    int lane = threadIdx.x & 31;
    if (e >= EDIM) return;
    float4 v = *(const float4*)(keys + e * KDIM + lane * 4);
    float ss = v.x * v.x + v.y * v.y + v.z * v.z + v.w * v.w;
#pragma unroll
    for (int o = 16; o; o >>= 1) ss += __shfl_xor_sync(0xffffffffu, ss, o);
    float inv = 1.f / fmaxf(sqrtf(ss), 1e-12f);
    float4 o4 = make_float4(v.x * inv, v.y * inv, v.z * inv, v.w * inv);
    *(float4*)(g_keysn + e * KDIM + lane * 4) = o4;
}

__global__ void zero_counts_kernel()
{
    if (threadIdx.x < EDIM) g_counts[threadIdx.x] = 0;
}

__global__ void router_kernel()
{
    int warp = threadIdx.x >> 5;
    int lane = threadIdx.x & 31;
    int t = blockIdx.x * 8 + warp;
    if (t >= BDIM) return;

    float4 v = *(const float4*)(g_pk + (size_t)t * KDIM + lane * 4);
    float ss = v.x * v.x + v.y * v.y + v.z * v.z + v.w * v.w;
#pragma unroll
    for (int o = 16; o; o >>= 1) ss += __shfl_xor_sync(0xffffffffu, ss, o);
    float inv = 1.f / fmaxf(sqrtf(ss), 1e-12f);

    float sims[EDIM];
#pragma unroll
    for (int e = 0; e < EDIM; e++) {
        float4 kv = *(const float4*)(g_keysn + e * KDIM + lane * 4);
        float d = v.x * kv.x + v.y * kv.y + v.z * kv.z + v.w * kv.w;
#pragma unroll
        for (int o = 16; o; o >>= 1) d += __shfl_xor_sync(0xffffffffu, d, o);
        sims[e] = d * inv;
    }

    if (lane == 0) {
        int i0 = 0; float v0 = sims[0];
#pragma unroll
        for (int e = 1; e < EDIM; e++) if (sims[e] > v0) { v0 = sims[e]; i0 = e; }
        int i1 = -1; float v1 = -1e30f;
#pragma unroll
        for (int e = 0; e < EDIM; e++) if (e != i0 && sims[e] > v1) { v1 = sims[e]; i1 = e; }

        float e1 = expf(v1 - v0);
        float s  = 1.f + e1;
        float w0 = 1.f / s;
        float w1 = e1 / s;

#pragma unroll
        for (int e = 0; e < EDIM; e++) {
            g_sim[t * EDIM + e] = sims[e];
            g_weights[t * EDIM + e] = (e == i0) ? w0 : ((e == i1) ? w1 : 0.f);
        }
        g_topi[t * TOPK + 0] = i0;
        g_topi[t * TOPK + 1] = i1;
        g_wslot[t * TOPK + 0] = w0;
        g_wslot[t * TOPK + 1] = w1;
        atomicAdd(&g_counts[i0], 1);
        atomicAdd(&g_counts[i1], 1);
    }
}

__global__ void scan_kernel()
{
    if (threadIdx.x == 0) {
        int off = 0;
        for (int e = 0; e < EDIM; e++) {
            g_offsets[e] = off;
            g_cursor[e]  = off;
            off += g_counts[e];
        }
        g_offsets[EDIM] = off;
    }
}

__global__ void scatter_kernel()
{
    int t = blockIdx.x * blockDim.x + threadIdx.x;
    if (t >= BDIM) return;
#pragma unroll
    for (int s = 0; s < TOPK; s++) {
        int e = g_topi[t * TOPK + s];
        int pos = atomicAdd(&g_cursor[e], 1);
        g_list[pos] = t;
        g_pos[t * TOPK + s] = pos;
    }
}

__global__ void combine_kernel(float* __restrict__ out)
{
    int t = blockIdx.x;
    float w0 = g_wslot[t * TOPK + 0];
    float w1 = g_wslot[t * TOPK + 1];
    size_t p0 = (size_t)g_pos[t * TOPK + 0];
    size_t p1 = (size_t)g_pos[t * TOPK + 1];
    for (int c = threadIdx.x; c < CDIM; c += blockDim.x)
        out[(size_t)t * CDIM + c] =
            w0 * g_eout[p0 * CDIM + c] + w1 * g_eout[p1 * CDIM + c];
}

__global__ void tail_writer_kernel(float* __restrict__ out, long long out_size)
{
    long long i = (long long)blockIdx.x * blockDim.x + threadIdx.x;
    const long long base_w = (long long)BDIM * CDIM;
    const long long n_w = BDIM * EDIM;
    const long long base_t = base_w + n_w;
    const long long n_t = BDIM * TOPK;
    const long long base_s = base_t + n_t;
    const long long n_s = BDIM * EDIM;
    if (i < n_w && base_w + i < out_size) out[base_w + i] = g_weights[i];
    if (i < n_t && base_t + i < out_size) out[base_t + i] = (float)g_topi[i];
    if (i < n_s && base_s + i < out_size) out[base_s + i] = g_sim[i];
}

// ---------------------------------------------------------------------------
// Launch
// ---------------------------------------------------------------------------
#define SG_SMEM (4 * 2 * 128 * 40 * (int)sizeof(__half))   // 81920 B
#define HG_SMEM (2 * 2 * 128 * 72 * (int)sizeof(__half))   // 73728 B

extern "C" void kernel_launch(void* const* d_in, const int* in_sizes, int n_in,
                              void* d_out, int out_size)
{
    const float* x    = (const float*)d_in[0];
    const float* fw1  = (const float*)d_in[1];
    const float* fb1  = (const float*)d_in[2];
    const float* fw2  = (const float*)d_in[3];
    const float* fb2  = (const float*)d_in[4];
    const float* kw   = (const float*)d_in[5];
    const float* kb   = (const float*)d_in[6];
    const float* keys = (const float*)d_in[7];
    const float* ew1  = (const float*)d_in[8];
    const float* eb1  = (const float*)d_in[9];
    const float* ew2  = (const float*)d_in[10];
    const float* eb2  = (const float*)d_in[11];
    const float* ew3  = (const float*)d_in[12];
    const float* eb3  = (const float*)d_in[13];
    float* out = (float*)d_out;

    cudaFuncSetAttribute(sgemm_k<0, true >, cudaFuncAttributeMaxDynamicSharedMemorySize, SG_SMEM);
    cudaFuncSetAttribute(sgemm_k<2, false>, cudaFuncAttributeMaxDynamicSharedMemorySize, SG_SMEM);
    cudaFuncSetAttribute(sgemm_k<7, false>, cudaFuncAttributeMaxDynamicSharedMemorySize, SG_SMEM);
    cudaFuncSetAttribute(hgemm_k<1, false>, cudaFuncAttributeMaxDynamicSharedMemorySize, HG_SMEM);
    cudaFuncSetAttribute(hgemm_k<3, true >, cudaFuncAttributeMaxDynamicSharedMemorySize, HG_SMEM);
    cudaFuncSetAttribute(hgemm_k<4, true >, cudaFuncAttributeMaxDynamicSharedMemorySize, HG_SMEM);
    cudaFuncSetAttribute(hgemm_k<5, false>, cudaFuncAttributeMaxDynamicSharedMemorySize, HG_SMEM);

    dim3 blk(256);
    dim3 tblk(32, 8);

    __half *xhi, *xlo, *fw1hi, *fw1lo, *fw2h, *fw2nhi, *fw2nlo, *kwhi, *kwlo;
    __half *wphi, *wplo, *ew1h, *ew2h, *ew3h;
    float  *zbias, *bp;
    cudaGetSymbolAddress((void**)&xhi,    g_xhi);
    cudaGetSymbolAddress((void**)&xlo,    g_xlo);
    cudaGetSymbolAddress((void**)&fw1hi,  g_fw1hi);
    cudaGetSymbolAddress((void**)&fw1lo,  g_fw1lo);
    cudaGetSymbolAddress((void**)&fw2h,   g_fw2h);
    cudaGetSymbolAddress((void**)&fw2nhi, g_fw2nhi);
    cudaGetSymbolAddress((void**)&fw2nlo, g_fw2nlo);
    cudaGetSymbolAddress((void**)&kwhi,   g_kwhi);
    cudaGetSymbolAddress((void**)&kwlo,   g_kwlo);
    cudaGetSymbolAddress((void**)&wphi,   g_wphi);
    cudaGetSymbolAddress((void**)&wplo,   g_wplo);
    cudaGetSymbolAddress((void**)&ew1h,   g_ew1h);
    cudaGetSymbolAddress((void**)&ew2h,   g_ew2h);
    cudaGetSymbolAddress((void**)&ew3h,   g_ew3h);
    cudaGetSymbolAddress((void**)&zbias,  g_zbias);
    cudaGetSymbolAddress((void**)&bp,     g_bp);

    // one-time conversions
    natsplit_k<<<BDIM * DDIM / 4 / 256, 256>>>(x, xhi, xlo);
    natsplit_k<<<HDIM * HDIM / 4 / 256, 256>>>(fw2, fw2nhi, fw2nlo);
    wsplit_k<<<dim3(HDIM / 32, DDIM / 32), tblk>>>(fw1, fw1hi, fw1lo, DDIM, HDIM);
    wsplit_k<<<dim3(KDIM / 32, HDIM / 32), tblk>>>(kw,  kwhi,  kwlo,  HDIM, KDIM);
    wconv_k<<<dim3(HDIM / 32,        HDIM / 32,  1   ), tblk>>>(fw2, fw2h, HDIM,  HDIM);
    wconv_k<<<dim3(HDIM / 32,        HDIM / 32,  EDIM), tblk>>>(ew1, ew1h, HDIM,  HDIM);
    wconv_k<<<dim3(H2DIM / 32,       HDIM / 32,  EDIM), tblk>>>(ew2, ew2h, HDIM,  H2DIM);
    wconv_k<<<dim3((CDIM + 31) / 32, H2DIM / 32, EDIM), tblk>>>(ew3, ew3h, H2DIM, CDIM);
    bprime_k<<<KDIM, 256>>>(fb2, kw, kb);

    // W'^T = kw^T @ fw2 (fp32-grade split output) : M=128, N=2048, K=2048
    sgemm_k<7, false><<<dim3(HDIM / 128, 1), blk, SG_SMEM>>>(fw2nhi, fw2nlo, zbias, HDIM, HDIM);

    keysn_kernel<<<1, 256>>>(keys);
    zero_counts_kernel<<<1, 32>>>();

    // stage0: x @ fw1 -> h split (fp32-grade, relu)
    sgemm_k<0, true ><<<dim3(HDIM / 128, BDIM / 128), blk, SG_SMEM>>>(fw1hi, fw1lo, fb1, HDIM, DDIM);
    // stage1: h @ fw2 -> feats (fp16-grade, experts only)
    hgemm_k<1, false><<<dim3(HDIM / 128, BDIM / 128, 1), blk, HG_SMEM>>>(fw2h, fb2, HDIM, HDIM);
    // routing projection: pk = h @ W' + b' (fp32-grade)
    sgemm_k<2, false><<<dim3(KDIM / 128, BDIM / 128), blk, SG_SMEM>>>(wphi, wplo, bp, KDIM, HDIM);

    router_kernel<<<BDIM / 8, 256>>>();
    scan_kernel<<<1, 32>>>();
    scatter_kernel<<<(BDIM + 255) / 256, 256>>>();

    // expert MLPs: pure fp16 tensor-core GEMMs on grouped rows
    hgemm_k<3, true ><<<dim3(HDIM / 128,         BDIM / 128, EDIM), blk, HG_SMEM>>>(ew1h, eb1, HDIM,  HDIM);
    hgemm_k<4, true ><<<dim3(H2DIM / 128,        BDIM / 128, EDIM), blk, HG_SMEM>>>(ew2h, eb2, H2DIM, HDIM);
    hgemm_k<5, false><<<dim3((CDIM + 127) / 128, BDIM / 128, EDIM), blk, HG_SMEM>>>(ew3h, eb3, CDIM,  H2DIM);

    combine_kernel<<<BDIM, 256>>>(out);
    tail_writer_kernel<<<(BDIM * EDIM + 255) / 256, 256>>>(out, (long long)out_size);
}

// round 12
// speedup vs baseline: 2.0050x; 1.0041x over previous
#include <cuda_runtime.h>
#include <cuda_fp16.h>
#include <math.h>
#include <stdint.h>

// ---------------------------------------------------------------------------
// Problem constants
// ---------------------------------------------------------------------------
#define BDIM   8192
#define DDIM   1024
#define HDIM   2048
#define H2DIM  1024
#define CDIM   1000
#define KDIM   128
#define EDIM   8
#define TOPK   2
#define MAXROWS (BDIM * TOPK)

// ---------------------------------------------------------------------------
// Scratch (device globals — no allocation allowed)
// ---------------------------------------------------------------------------
__device__ __half g_xhi  [(size_t)BDIM * DDIM];
__device__ __half g_xlo  [(size_t)BDIM * DDIM];
__device__ __half g_hhi  [(size_t)BDIM * HDIM];
__device__ __half g_hlo  [(size_t)BDIM * HDIM];
__device__ __half g_featshi[(size_t)BDIM * HDIM];
__device__ float  g_pk   [(size_t)BDIM * KDIM];
__device__ float  g_keysn[EDIM * KDIM];
__device__ float  g_sim  [BDIM * EDIM];
__device__ float  g_weights[BDIM * EDIM];
__device__ float  g_wslot[BDIM * TOPK];
__device__ int    g_topi [BDIM * TOPK];
__device__ int    g_counts[EDIM];
__device__ int    g_offsets[EDIM + 1];
__device__ int    g_cursor[EDIM];
__device__ int    g_list [MAXROWS];
__device__ int    g_pos  [BDIM * TOPK];
__device__ __half g_h1h  [(size_t)MAXROWS * HDIM];
__device__ __half g_h2h  [(size_t)MAXROWS * H2DIM];
__device__ float  g_eout [(size_t)MAXROWS * CDIM];
// converted weights
__device__ __half g_fw1hi[(size_t)HDIM * DDIM];   // fw1^T split  [H][D]
__device__ __half g_fw1lo[(size_t)HDIM * DDIM];
__device__ __half g_fw2h [(size_t)HDIM * HDIM];   // fw2^T single [Hout][Hin]
__device__ __half g_fw2nhi[(size_t)HDIM * HDIM];  // fw2 natural split [Hin][Hout]
__device__ __half g_fw2nlo[(size_t)HDIM * HDIM];
__device__ __half g_kwhi [(size_t)KDIM * HDIM];   // kw^T split   [K][H]
__device__ __half g_kwlo [(size_t)KDIM * HDIM];
__device__ __half g_wphi [(size_t)KDIM * HDIM];   // W'^T split   [K][H]
__device__ __half g_wplo [(size_t)KDIM * HDIM];
__device__ float  g_bp   [KDIM];                  // b' = fb2@kw + kb
__device__ float  g_zbias[HDIM];                  // zeros (static init)
__device__ __half g_ew1h [(size_t)EDIM * HDIM  * HDIM];
__device__ __half g_ew2h [(size_t)EDIM * H2DIM * HDIM];
__device__ __half g_ew3h [(size_t)EDIM * CDIM  * H2DIM];

#define LO_SCALE 4096.0f
#define LO_INV   (1.0f / 4096.0f)

// ---------------------------------------------------------------------------
// helpers
// ---------------------------------------------------------------------------
__device__ __forceinline__ void mma_f16(float c[4],
                                        const uint32_t a[4],
                                        const uint32_t b[2]) {
    asm volatile(
        "mma.sync.aligned.m16n8k16.row.col.f32.f16.f16.f32 "
        "{%0,%1,%2,%3}, {%4,%5,%6,%7}, {%8,%9}, {%0,%1,%2,%3};"
        : "+f"(c[0]), "+f"(c[1]), "+f"(c[2]), "+f"(c[3])
        : "r"(a[0]), "r"(a[1]), "r"(a[2]), "r"(a[3]),
          "r"(b[0]), "r"(b[1]));
}
__device__ __forceinline__ void cp16(void* dst, const void* src, bool valid) {
    uint32_t d = (uint32_t)__cvta_generic_to_shared(dst);
    int sz = valid ? 16 : 0;
    asm volatile("cp.async.cg.shared.global [%0], [%1], 16, %2;"
                 :: "r"(d), "l"(src), "r"(sz));
}
__device__ __forceinline__ void split_f32(float v, __half& hi, __half& lo) {
    hi = __float2half(v);
    lo = __float2half((v - __half2float(hi)) * LO_SCALE);
}

// ---------------------------------------------------------------------------
// One-time conversions (R10-verbatim)
// ---------------------------------------------------------------------------
__global__ void natsplit_k(const float* __restrict__ W,
                           __half* __restrict__ Whi, __half* __restrict__ Wlo)
{
    size_t i = ((size_t)blockIdx.x * 256 + threadIdx.x) * 4;
    float4 v = *(const float4*)(W + i);
    __half h0, l0, h1, l1, h2, l2, h3, l3;
    split_f32(v.x, h0, l0); split_f32(v.y, h1, l1);
    split_f32(v.z, h2, l2); split_f32(v.w, h3, l3);
    *(__half2*)&Whi[i]     = __halves2half2(h0, h1);
    *(__half2*)&Whi[i + 2] = __halves2half2(h2, h3);
    *(__half2*)&Wlo[i]     = __halves2half2(l0, l1);
    *(__half2*)&Wlo[i + 2] = __halves2half2(l2, l3);
}

__global__ void wsplit_k(const float* __restrict__ W,
                         __half* __restrict__ Whi, __half* __restrict__ Wlo,
                         int K, int N)
{
    __shared__ float t[32][33];
    int k0 = blockIdx.y * 32;
    int n0 = blockIdx.x * 32;
#pragma unroll
    for (int j = 0; j < 4; j++)
        t[threadIdx.y + j * 8][threadIdx.x] =
            W[(size_t)(k0 + threadIdx.y + j * 8) * N + n0 + threadIdx.x];
    __syncthreads();
#pragma unroll
    for (int j = 0; j < 4; j++) {
        int n = n0 + threadIdx.y + j * 8;
        int k = k0 + threadIdx.x;
        float val = t[threadIdx.x][threadIdx.y + j * 8];
        __half hi, lo;
        split_f32(val, hi, lo);
        Whi[(size_t)n * K + k] = hi;
        Wlo[(size_t)n * K + k] = lo;
    }
}

__global__ void wconv_k(const float* __restrict__ Wg, __half* __restrict__ Wtg,
                        int K, int N)
{
    const float* W  = Wg  + (size_t)blockIdx.z * K * N;
    __half*      Wt = Wtg + (size_t)blockIdx.z * N * K;
    __shared__ float t[32][33];
    int k0 = blockIdx.y * 32;
    int n0 = blockIdx.x * 32;
#pragma unroll
    for (int j = 0; j < 4; j++) {
        int n = n0 + threadIdx.x;
        if (n < N) t[threadIdx.y + j * 8][threadIdx.x] =
            W[(size_t)(k0 + threadIdx.y + j * 8) * N + n];
    }
    __syncthreads();
#pragma unroll
    for (int j = 0; j < 4; j++) {
        int n = n0 + threadIdx.y + j * 8;
        int k = k0 + threadIdx.x;
        if (n < N) Wt[(size_t)n * K + k] =
            __float2half(t[threadIdx.x][threadIdx.y + j * 8]);
    }
}

__global__ void bprime_k(const float* __restrict__ fb2,
                         const float* __restrict__ kw,
                         const float* __restrict__ kb)
{
    int j = blockIdx.x;
    float s = 0.f;
    for (int m = threadIdx.x; m < HDIM; m += 256)
        s += fb2[m] * kw[(size_t)m * KDIM + j];
    __shared__ float red[8];
#pragma unroll
    for (int o = 16; o; o >>= 1) s += __shfl_xor_sync(0xffffffffu, s, o);
    if ((threadIdx.x & 31) == 0) red[threadIdx.x >> 5] = s;
    __syncthreads();
    if (threadIdx.x == 0) {
        float t = 0.f;
#pragma unroll
        for (int w = 0; w < 8; w++) t += red[w];
        g_bp[j] = t + kb[j];
    }
}

// ---------------------------------------------------------------------------
// fp16 2-term-split GEMM (R10-verbatim; STAGE 0 and 7 only now)
// ---------------------------------------------------------------------------
#define SBK 32

template<int STAGE, bool RELU>
__global__ __launch_bounds__(256) void sgemm_k(const __half* __restrict__ Whi,
                                               const __half* __restrict__ Wlo,
                                               const float* __restrict__ Bias,
                                               int N, int Kd)
{
    extern __shared__ __half sms[];
    __half (*S)[2][128][40] = (__half(*)[2][128][40])sms;

    const __half *Ahi, *Alo;
    if (STAGE == 0)      { Ahi = g_xhi;  Alo = g_xlo;  }
    else if (STAGE == 2) { Ahi = g_hhi;  Alo = g_hlo;  }
    else                 { Ahi = g_kwhi; Alo = g_kwlo; }

    const int tileM = blockIdx.y * 128;
    const int tileN = blockIdx.x * 128;

    const int tid  = threadIdx.x;
    const int lane = tid & 31;
    const int wid  = tid >> 5;
    const int g    = lane >> 2;
    const int tig  = lane & 3;
    const int warpM = wid & 1;
    const int warpN = wid >> 1;

    const int rr = tid >> 2;
    const int cc = (tid & 3) * 8;

    const size_t aoff = (size_t)(tileM + rr) * Kd + cc;
    const size_t boff = (size_t)(tileN + rr) * Kd + cc;
    const size_t rstep = (size_t)64 * Kd;

    float acc [4][4][4];
    float accx[4][4][4];
#pragma unroll
    for (int i = 0; i < 4; i++)
#pragma unroll
        for (int j = 0; j < 4; j++)
#pragma unroll
            for (int r = 0; r < 4; r++) { acc[i][j][r] = 0.f; accx[i][j][r] = 0.f; }

    const int KT = Kd / SBK;

    auto load_tile = [&](int k0, int buf) {
#pragma unroll
        for (int it = 0; it < 2; it++) {
            cp16(&S[0][buf][rr + it * 64][cc], Ahi + aoff + it * rstep + k0, true);
            cp16(&S[1][buf][rr + it * 64][cc], Alo + aoff + it * rstep + k0, true);
            cp16(&S[2][buf][rr + it * 64][cc], Whi + boff + it * rstep + k0, true);
            cp16(&S[3][buf][rr + it * 64][cc], Wlo + boff + it * rstep + k0, true);
        }
        asm volatile("cp.async.commit_group;");
    };

    load_tile(0, 0);

    for (int kt = 0; kt < KT; kt++) {
        const int buf = kt & 1;
        if (kt + 1 < KT) {
            load_tile((kt + 1) * SBK, (kt + 1) & 1);
            asm volatile("cp.async.wait_group 1;");
        } else {
            asm volatile("cp.async.wait_group 0;");
        }
        __syncthreads();

#pragma unroll
        for (int ks = 0; ks < 2; ks++) {
            const int k16 = ks * 16;
            uint32_t bh[4][2], bl[4][2];
#pragma unroll
            for (int nf = 0; nf < 4; nf++) {
                int n = warpN * 32 + nf * 8 + g;
                bh[nf][0] = *(const uint32_t*)&S[2][buf][n][k16 + 2 * tig    ];
                bh[nf][1] = *(const uint32_t*)&S[2][buf][n][k16 + 2 * tig + 8];
                bl[nf][0] = *(const uint32_t*)&S[3][buf][n][k16 + 2 * tig    ];
                bl[nf][1] = *(const uint32_t*)&S[3][buf][n][k16 + 2 * tig + 8];
            }
#pragma unroll
            for (int mf = 0; mf < 4; mf++) {
                int m = warpM * 64 + mf * 16 + g;
                uint32_t ah[4], al[4];
                ah[0] = *(const uint32_t*)&S[0][buf][m    ][k16 + 2 * tig    ];
                ah[1] = *(const uint32_t*)&S[0][buf][m + 8][k16 + 2 * tig    ];
                ah[2] = *(const uint32_t*)&S[0][buf][m    ][k16 + 2 * tig + 8];
                ah[3] = *(const uint32_t*)&S[0][buf][m + 8][k16 + 2 * tig + 8];
                al[0] = *(const uint32_t*)&S[1][buf][m    ][k16 + 2 * tig    ];
                al[1] = *(const uint32_t*)&S[1][buf][m + 8][k16 + 2 * tig    ];
                al[2] = *(const uint32_t*)&S[1][buf][m    ][k16 + 2 * tig + 8];
                al[3] = *(const uint32_t*)&S[1][buf][m + 8][k16 + 2 * tig + 8];
#pragma unroll
                for (int nf = 0; nf < 4; nf++) {
                    mma_f16(acc [mf][nf], ah, bh[nf]);
                    mma_f16(accx[mf][nf], ah, bl[nf]);
                    mma_f16(accx[mf][nf], al, bh[nf]);
                }
            }
        }
        __syncthreads();
    }

#pragma unroll
    for (int mf = 0; mf < 4; mf++) {
        int row0 = tileM + warpM * 64 + mf * 16 + g;
        int row1 = row0 + 8;
#pragma unroll
        for (int nf = 0; nf < 4; nf++) {
            int col0 = tileN + warpN * 32 + nf * 8 + tig * 2;
            int col1 = col0 + 1;
            float b0 = Bias[col0];
            float b1 = Bias[col1];
            float v00 = acc[mf][nf][0] + accx[mf][nf][0] * LO_INV + b0;
            float v01 = acc[mf][nf][1] + accx[mf][nf][1] * LO_INV + b1;
            float v10 = acc[mf][nf][2] + accx[mf][nf][2] * LO_INV + b0;
            float v11 = acc[mf][nf][3] + accx[mf][nf][3] * LO_INV + b1;
            if (RELU) {
                v00 = fmaxf(v00, 0.f); v01 = fmaxf(v01, 0.f);
                v10 = fmaxf(v10, 0.f); v11 = fmaxf(v11, 0.f);
            }
            if (STAGE == 2) {
                g_pk[(size_t)row0 * N + col0] = v00;
                g_pk[(size_t)row0 * N + col1] = v01;
                g_pk[(size_t)row1 * N + col0] = v10;
                g_pk[(size_t)row1 * N + col1] = v11;
            } else {
                __half* Hi = (STAGE == 0) ? g_hhi : g_wphi;
                __half* Lo = (STAGE == 0) ? g_hlo : g_wplo;
                __half h, l;
                split_f32(v00, h, l);
                Hi[(size_t)row0 * N + col0] = h; Lo[(size_t)row0 * N + col0] = l;
                split_f32(v01, h, l);
                Hi[(size_t)row0 * N + col1] = h; Lo[(size_t)row0 * N + col1] = l;
                split_f32(v10, h, l);
                Hi[(size_t)row1 * N + col0] = h; Lo[(size_t)row1 * N + col0] = l;
                split_f32(v11, h, l);
                Hi[(size_t)row1 * N + col1] = h; Lo[(size_t)row1 * N + col1] = l;
            }
        }
    }
}

// ---------------------------------------------------------------------------
// Pure fp16 GEMM (R10-verbatim; expert stages 3/4/5)
// ---------------------------------------------------------------------------
#define HBK 64

template<int STAGE, bool RELU>
__global__ __launch_bounds__(256) void hgemm_k(const __half* __restrict__ Wt,
                                               const float* __restrict__ Biasg,
                                               int N, int Kd)
{
    extern __shared__ __half smh[];
    __half (*Ah)[128][72] = (__half(*)[128][72])smh;
    __half (*Bh)[128][72] = (__half(*)[128][72])(smh + 2 * 128 * 72);

    int M;
    const __half* B;
    const float* Bias;
    const __half* A;
    __half* Ch = nullptr;
    float*  Cf = nullptr;
    const int* gather = nullptr;

    {
        int e  = blockIdx.z;
        int m0 = g_offsets[e];
        M = g_offsets[e + 1] - m0;
        B    = Wt    + (size_t)e * N * Kd;
        Bias = Biasg + (size_t)e * N;
        if (STAGE == 3)      { A = g_featshi; gather = g_list + m0; Ch = g_h1h + (size_t)m0 * N; }
        else if (STAGE == 4) { A = g_h1h + (size_t)m0 * Kd;         Ch = g_h2h + (size_t)m0 * N; }
        else                 { A = g_h2h + (size_t)m0 * Kd;         Cf = g_eout + (size_t)m0 * N; }
    }

    const int tileM = blockIdx.y * 128;
    if (tileM >= M) return;
    const int tileN = blockIdx.x * 128;

    const int tid  = threadIdx.x;
    const int lane = tid & 31;
    const int wid  = tid >> 5;
    const int g    = lane >> 2;
    const int tig  = lane & 3;
    const int warpM = wid & 1;
    const int warpN = wid >> 1;

    const __half* aptr[4];
    bool av[4];
#pragma unroll
    for (int it = 0; it < 4; it++) {
        int r = (tid >> 3) + it * 32;
        int grow = tileM + r;
        av[it] = (grow < M);
        size_t arow = 0;
        if (av[it]) arow = (STAGE == 3) ? (size_t)gather[grow] : (size_t)grow;
        aptr[it] = A + arow * Kd + (tid & 7) * 8;
    }
    const __half* bptr[4];
    bool bvv[4];
#pragma unroll
    for (int it = 0; it < 4; it++) {
        int r = (tid >> 3) + it * 32;
        int gn = tileN + r;
        bvv[it] = (gn < N);
        bptr[it] = B + (size_t)(bvv[it] ? gn : 0) * Kd + (tid & 7) * 8;
    }

    float acc[4][4][4];
#pragma unroll
    for (int i = 0; i < 4; i++)
#pragma unroll
        for (int j = 0; j < 4; j++)
#pragma unroll
            for (int r = 0; r < 4; r++) acc[i][j][r] = 0.f;

    const int KT = Kd / HBK;

    auto load_tile = [&](int k0, int buf) {
#pragma unroll
        for (int it = 0; it < 4; it++) {
            int r = (tid >> 3) + it * 32;
            cp16(&Ah[buf][r][(tid & 7) * 8], aptr[it] + k0, av[it]);
        }
#pragma unroll
        for (int it = 0; it < 4; it++) {
            int r = (tid >> 3) + it * 32;
            cp16(&Bh[buf][r][(tid & 7) * 8], bptr[it] + k0, bvv[it]);
        }
        asm volatile("cp.async.commit_group;");
    };

    load_tile(0, 0);

    for (int kt = 0; kt < KT; kt++) {
        const int buf = kt & 1;
        if (kt + 1 < KT) {
            load_tile((kt + 1) * HBK, (kt + 1) & 1);
            asm volatile("cp.async.wait_group 1;");
        } else {
            asm volatile("cp.async.wait_group 0;");
        }
        __syncthreads();

#pragma unroll
        for (int ks = 0; ks < 4; ks++) {
            const int k16 = ks * 16;
            uint32_t bf[4][2];
#pragma unroll
            for (int nf = 0; nf < 4; nf++) {
                int n = warpN * 32 + nf * 8 + g;
                bf[nf][0] = *(const uint32_t*)&Bh[buf][n][k16 + 2 * tig    ];
                bf[nf][1] = *(const uint32_t*)&Bh[buf][n][k16 + 2 * tig + 8];
            }
#pragma unroll
            for (int mf = 0; mf < 4; mf++) {
                int m = warpM * 64 + mf * 16 + g;
                uint32_t af[4];
                af[0] = *(const uint32_t*)&Ah[buf][m    ][k16 + 2 * tig    ];
                af[1] = *(const uint32_t*)&Ah[buf][m + 8][k16 + 2 * tig    ];
                af[2] = *(const uint32_t*)&Ah[buf][m    ][k16 + 2 * tig + 8];
                af[3] = *(const uint32_t*)&Ah[buf][m + 8][k16 + 2 * tig + 8];
#pragma unroll
                for (int nf = 0; nf < 4; nf++)
                    mma_f16(acc[mf][nf], af, bf[nf]);
            }
        }
        __syncthreads();
    }

#pragma unroll
    for (int mf = 0; mf < 4; mf++) {
        int row0 = tileM + warpM * 64 + mf * 16 + g;
        int row1 = row0 + 8;
#pragma unroll
        for (int nf = 0; nf < 4; nf++) {
            int col0 = tileN + warpN * 32 + nf * 8 + tig * 2;
            int col1 = col0 + 1;
            float b0 = (col0 < N) ? Bias[col0] : 0.f;
            float b1 = (col1 < N) ? Bias[col1] : 0.f;
            float v00 = acc[mf][nf][0] + b0;
            float v01 = acc[mf][nf][1] + b1;
            float v10 = acc[mf][nf][2] + b0;
            float v11 = acc[mf][nf][3] + b1;
            if (RELU) {
                v00 = fmaxf(v00, 0.f); v01 = fmaxf(v01, 0.f);
                v10 = fmaxf(v10, 0.f); v11 = fmaxf(v11, 0.f);
            }
            if (STAGE == 5) {
                if (row0 < M) {
                    if (col0 < N) Cf[(size_t)row0 * N + col0] = v00;
                    if (col1 < N) Cf[(size_t)row0 * N + col1] = v01;
                }
                if (row1 < M) {
                    if (col0 < N) Cf[(size_t)row1 * N + col0] = v10;
                    if (col1 < N) Cf[(size_t)row1 * N + col1] = v11;
                }
            } else {
                if (row0 < M) {
                    if (col0 < N) Ch[(size_t)row0 * N + col0] = __float2half(v00);
                    if (col1 < N) Ch[(size_t)row0 * N + col1] = __float2half(v01);
                }
                if (row1 < M) {
                    if (col0 < N) Ch[(size_t)row1 * N + col0] = __float2half(v10);
                    if (col1 < N) Ch[(size_t)row1 * N + col1] = __float2half(v11);
                }
            }
        }
    }
}

// ---------------------------------------------------------------------------
// NEW (only change vs R10): stage1 + stage2 fused into one wave.
//   blockIdx.x == 0 : stage2 split-GEMM  h @ W' + b' -> g_pk   (fp32)
//   blockIdx.x >= 1 : stage1 fp16 GEMM   h @ fw2 + fb2 -> g_featshi
// Grid (17, 64). Both paths are verbatim copies of the R10 bodies with
// STAGE constants resolved. SMEM = 81920 (max of the two layouts).
// ---------------------------------------------------------------------------
__global__ __launch_bounds__(256) void fused12_k(const float* __restrict__ fb2)
{
    extern __shared__ __half smf[];
    const int tid  = threadIdx.x;
    const int lane = tid & 31;
    const int wid  = tid >> 5;
    const int g    = lane >> 2;
    const int tig  = lane & 3;
    const int warpM = wid & 1;
    const int warpN = wid >> 1;

    if (blockIdx.x == 0) {
        // ----- stage2: split GEMM, tileN=0, N=KDIM, Kd=HDIM -----
        __half (*S)[2][128][40] = (__half(*)[2][128][40])smf;
        const __half* Ahi = g_hhi;
        const __half* Alo = g_hlo;
        const __half* Whi = g_wphi;
        const __half* Wlo = g_wplo;
        const int N  = KDIM;
        const int Kd = HDIM;
        const int tileM = blockIdx.y * 128;
        const int tileN = 0;

        const int rr = tid >> 2;
        const int cc = (tid & 3) * 8;
        const size_t aoff = (size_t)(tileM + rr) * Kd + cc;
        const size_t boff = (size_t)(tileN + rr) * Kd + cc;
        const size_t rstep = (size_t)64 * Kd;

        float acc [4][4][4];
        float accx[4][4][4];
#pragma unroll
        for (int i = 0; i < 4; i++)
#pragma unroll
            for (int j = 0; j < 4; j++)
#pragma unroll
                for (int r = 0; r < 4; r++) { acc[i][j][r] = 0.f; accx[i][j][r] = 0.f; }

        const int KT = Kd / SBK;

        auto load_tile = [&](int k0, int buf) {
#pragma unroll
            for (int it = 0; it < 2; it++) {
                cp16(&S[0][buf][rr + it * 64][cc], Ahi + aoff + it * rstep + k0, true);
                cp16(&S[1][buf][rr + it * 64][cc], Alo + aoff + it * rstep + k0, true);
                cp16(&S[2][buf][rr + it * 64][cc], Whi + boff + it * rstep + k0, true);
                cp16(&S[3][buf][rr + it * 64][cc], Wlo + boff + it * rstep + k0, true);
            }
            asm volatile("cp.async.commit_group;");
        };

        load_tile(0, 0);

        for (int kt = 0; kt < KT; kt++) {
            const int buf = kt & 1;
            if (kt + 1 < KT) {
                load_tile((kt + 1) * SBK, (kt + 1) & 1);
                asm volatile("cp.async.wait_group 1;");
            } else {
                asm volatile("cp.async.wait_group 0;");
            }
            __syncthreads();

#pragma unroll
            for (int ks = 0; ks < 2; ks++) {
                const int k16 = ks * 16;
                uint32_t bh[4][2], bl[4][2];
#pragma unroll
                for (int nf = 0; nf < 4; nf++) {
                    int n = warpN * 32 + nf * 8 + g;
                    bh[nf][0] = *(const uint32_t*)&S[2][buf][n][k16 + 2 * tig    ];
                    bh[nf][1] = *(const uint32_t*)&S[2][buf][n][k16 + 2 * tig + 8];
                    bl[nf][0] = *(const uint32_t*)&S[3][buf][n][k16 + 2 * tig    ];
                    bl[nf][1] = *(const uint32_t*)&S[3][buf][n][k16 + 2 * tig + 8];
                }
#pragma unroll
                for (int mf = 0; mf < 4; mf++) {
                    int m = warpM * 64 + mf * 16 + g;
                    uint32_t ah[4], al[4];
                    ah[0] = *(const uint32_t*)&S[0][buf][m    ][k16 + 2 * tig    ];
                    ah[1] = *(const uint32_t*)&S[0][buf][m + 8][k16 + 2 * tig    ];
                    ah[2] = *(const uint32_t*)&S[0][buf][m    ][k16 + 2 * tig + 8];
                    ah[3] = *(const uint32_t*)&S[0][buf][m + 8][k16 + 2 * tig + 8];
                    al[0] = *(const uint32_t*)&S[1][buf][m    ][k16 + 2 * tig    ];
                    al[1] = *(const uint32_t*)&S[1][buf][m + 8][k16 + 2 * tig    ];
                    al[2] = *(const uint32_t*)&S[1][buf][m    ][k16 + 2 * tig + 8];
                    al[3] = *(const uint32_t*)&S[1][buf][m + 8][k16 + 2 * tig + 8];
#pragma unroll
                    for (int nf = 0; nf < 4; nf++) {
                        mma_f16(acc [mf][nf], ah, bh[nf]);
                        mma_f16(accx[mf][nf], ah, bl[nf]);
                        mma_f16(accx[mf][nf], al, bh[nf]);
                    }
                }
            }
            __syncthreads();
        }

#pragma unroll
        for (int mf = 0; mf < 4; mf++) {
            int row0 = tileM + warpM * 64 + mf * 16 + g;
            int row1 = row0 + 8;
#pragma unroll
            for (int nf = 0; nf < 4; nf++) {
                int col0 = tileN + warpN * 32 + nf * 8 + tig * 2;
                int col1 = col0 + 1;
                float b0 = g_bp[col0];
                float b1 = g_bp[col1];
                g_pk[(size_t)row0 * N + col0] = acc[mf][nf][0] + accx[mf][nf][0] * LO_INV + b0;
                g_pk[(size_t)row0 * N + col1] = acc[mf][nf][1] + accx[mf][nf][1] * LO_INV + b1;
                g_pk[(size_t)row1 * N + col0] = acc[mf][nf][2] + accx[mf][nf][2] * LO_INV + b0;
                g_pk[(size_t)row1 * N + col1] = acc[mf][nf][3] + accx[mf][nf][3] * LO_INV + b1;
            }
        }
    } else {
        // ----- stage1: fp16 GEMM h @ fw2 -> g_featshi -----
        __half (*Ah)[128][72] = (__half(*)[128][72])smf;
        __half (*Bh)[128][72] = (__half(*)[128][72])(smf + 2 * 128 * 72);

        const __half* A = g_hhi;
        const __half* B = g_fw2h;
        const int N  = HDIM;
        const int Kd = HDIM;
        const int M  = BDIM;
        const int tileM = blockIdx.y * 128;
        const int tileN = (blockIdx.x - 1) * 128;

        const __half* aptr[4];
#pragma unroll
        for (int it = 0; it < 4; it++) {
            int r = (tid >> 3) + it * 32;
            aptr[it] = A + (size_t)(tileM + r) * Kd + (tid & 7) * 8;
        }
        const __half* bptr[4];
#pragma unroll
        for (int it = 0; it < 4; it++) {
            int r = (tid >> 3) + it * 32;
            bptr[it] = B + (size_t)(tileN + r) * Kd + (tid & 7) * 8;
        }

        float acc[4][4][4];
#pragma unroll
        for (int i = 0; i < 4; i++)
#pragma unroll
            for (int j = 0; j < 4; j++)
#pragma unroll
                for (int r = 0; r < 4; r++) acc[i][j][r] = 0.f;

        const int KT = Kd / HBK;

        auto load_tile = [&](int k0, int buf) {
#pragma unroll
            for (int it = 0; it < 4; it++) {
                int r = (tid >> 3) + it * 32;
                cp16(&Ah[buf][r][(tid & 7) * 8], aptr[it] + k0, true);
            }
#pragma unroll
            for (int it = 0; it < 4; it++) {
                int r = (tid >> 3) + it * 32;
                cp16(&Bh[buf][r][(tid & 7) * 8], bptr[it] + k0, true);
            }
            asm volatile("cp.async.commit_group;");
        };

        load_tile(0, 0);

        for (int kt = 0; kt < KT; kt++) {
            const int buf = kt & 1;
            if (kt + 1 < KT) {
                load_tile((kt + 1) * HBK, (kt + 1) & 1);
                asm volatile("cp.async.wait_group 1;");
            } else {
                asm volatile("cp.async.wait_group 0;");
            }
            __syncthreads();

#pragma unroll
            for (int ks = 0; ks < 4; ks++) {
                const int k16 = ks * 16;
                uint32_t bf[4][2];
#pragma unroll
                for (int nf = 0; nf < 4; nf++) {
                    int n = warpN * 32 + nf * 8 + g;
                    bf[nf][0] = *(const uint32_t*)&Bh[buf][n][k16 + 2 * tig    ];
                    bf[nf][1] = *(const uint32_t*)&Bh[buf][n][k16 + 2 * tig + 8];
                }
#pragma unroll
                for (int mf = 0; mf < 4; mf++) {
                    int m = warpM * 64 + mf * 16 + g;
                    uint32_t af[4];
                    af[0] = *(const uint32_t*)&Ah[buf][m    ][k16 + 2 * tig    ];
                    af[1] = *(const uint32_t*)&Ah[buf][m + 8][k16 + 2 * tig    ];
                    af[2] = *(const uint32_t*)&Ah[buf][m    ][k16 + 2 * tig + 8];
                    af[3] = *(const uint32_t*)&Ah[buf][m + 8][k16 + 2 * tig + 8];
#pragma unroll
                    for (int nf = 0; nf < 4; nf++)
                        mma_f16(acc[mf][nf], af, bf[nf]);
                }
            }
            __syncthreads();
        }

#pragma unroll
        for (int mf = 0; mf < 4; mf++) {
            int row0 = tileM + warpM * 64 + mf * 16 + g;
            int row1 = row0 + 8;
#pragma unroll
            for (int nf = 0; nf < 4; nf++) {
                int col0 = tileN + warpN * 32 + nf * 8 + tig * 2;
                int col1 = col0 + 1;
                float b0 = fb2[col0];
                float b1 = fb2[col1];
                g_featshi[(size_t)row0 * N + col0] = __float2half(acc[mf][nf][0] + b0);
                g_featshi[(size_t)row0 * N + col1] = __float2half(acc[mf][nf][1] + b1);
                g_featshi[(size_t)row1 * N + col0] = __float2half(acc[mf][nf][2] + b0);
                g_featshi[(size_t)row1 * N + col1] = __float2half(acc[mf][nf][3] + b1);
            }
        }
    }
}

// ---------------------------------------------------------------------------
// keys normalization / routing / grouping / combine (R10-verbatim)
// ---------------------------------------------------------------------------
__global__ void keysn_kernel(const float* __restrict__ keys)
{
    int e    = threadIdx.x >> 5;
    int lane = threadIdx.x & 31;
    if (e >= EDIM) return;
    float4 v = *(const float4*)(keys + e * KDIM + lane * 4);
    float ss = v.x * v.x + v.y * v.y + v.z * v.z + v.w * v.w;
#pragma unroll
    for (int o = 16; o; o >>= 1) ss += __shfl_xor_sync(0xffffffffu, ss, o);
    float inv = 1.f / fmaxf(sqrtf(ss), 1e-12f);
    float4 o4 = make_float4(v.x * inv, v.y * inv, v.z * inv, v.w * inv);
    *(float4*)(g_keysn + e * KDIM + lane * 4) = o4;
}

__global__ void zero_counts_kernel()
{
    if (threadIdx.x < EDIM) g_counts[threadIdx.x] = 0;
}

__global__ void router_kernel()
{
    int warp = threadIdx.x >> 5;
    int lane = threadIdx.x & 31;
    int t = blockIdx.x * 8 + warp;
    if (t >= BDIM) return;

    float4 v = *(const float4*)(g_pk + (size_t)t * KDIM + lane * 4);
    float ss = v.x * v.x + v.y * v.y + v.z * v.z + v.w * v.w;
#pragma unroll
    for (int o = 16; o; o >>= 1) ss += __shfl_xor_sync(0xffffffffu, ss, o);
    float inv = 1.f / fmaxf(sqrtf(ss), 1e-12f);

    float sims[EDIM];
#pragma unroll
    for (int e = 0; e < EDIM; e++) {
        float4 kv = *(const float4*)(g_keysn + e * KDIM + lane * 4);
        float d = v.x * kv.x + v.y * kv.y + v.z * kv.z + v.w * kv.w;
#pragma unroll
        for (int o = 16; o; o >>= 1) d += __shfl_xor_sync(0xffffffffu, d, o);
        sims[e] = d * inv;
    }

    if (lane == 0) {
        int i0 = 0; float v0 = sims[0];
#pragma unroll
        for (int e = 1; e < EDIM; e++) if (sims[e] > v0) { v0 = sims[e]; i0 = e; }
        int i1 = -1; float v1 = -1e30f;
#pragma unroll
        for (int e = 0; e < EDIM; e++) if (e != i0 && sims[e] > v1) { v1 = sims[e]; i1 = e; }

        float e1 = expf(v1 - v0);
        float s  = 1.f + e1;
        float w0 = 1.f / s;
        float w1 = e1 / s;

#pragma unroll
        for (int e = 0; e < EDIM; e++) {
            g_sim[t * EDIM + e] = sims[e];
            g_weights[t * EDIM + e] = (e == i0) ? w0 : ((e == i1) ? w1 : 0.f);
        }
        g_topi[t * TOPK + 0] = i0;
        g_topi[t * TOPK + 1] = i1;
        g_wslot[t * TOPK + 0] = w0;
        g_wslot[t * TOPK + 1] = w1;
        atomicAdd(&g_counts[i0], 1);
        atomicAdd(&g_counts[i1], 1);
    }
}

__global__ void scan_kernel()
{
    if (threadIdx.x == 0) {
        int off = 0;
        for (int e = 0; e < EDIM; e++) {
            g_offsets[e] = off;
            g_cursor[e]  = off;
            off += g_counts[e];
        }
        g_offsets[EDIM] = off;
    }
}

__global__ void scatter_kernel()
{
    int t = blockIdx.x * blockDim.x + threadIdx.x;
    if (t >= BDIM) return;
#pragma unroll
    for (int s = 0; s < TOPK; s++) {
        int e = g_topi[t * TOPK + s];
        int pos = atomicAdd(&g_cursor[e], 1);
        g_list[pos] = t;
        g_pos[t * TOPK + s] = pos;
    }
}

__global__ void combine_kernel(float* __restrict__ out)
{
    int t = blockIdx.x;
    float w0 = g_wslot[t * TOPK + 0];
    float w1 = g_wslot[t * TOPK + 1];
    size_t p0 = (size_t)g_pos[t * TOPK + 0];
    size_t p1 = (size_t)g_pos[t * TOPK + 1];
    for (int c = threadIdx.x; c < CDIM; c += blockDim.x)
        out[(size_t)t * CDIM + c] =
            w0 * g_eout[p0 * CDIM + c] + w1 * g_eout[p1 * CDIM + c];
}

__global__ void tail_writer_kernel(float* __restrict__ out, long long out_size)
{
    long long i = (long long)blockIdx.x * blockDim.x + threadIdx.x;
    const long long base_w = (long long)BDIM * CDIM;
    const long long n_w = BDIM * EDIM;
    const long long base_t = base_w + n_w;
    const long long n_t = BDIM * TOPK;
    const long long base_s = base_t + n_t;
    const long long n_s = BDIM * EDIM;
    if (i < n_w && base_w + i < out_size) out[base_w + i] = g_weights[i];
    if (i < n_t && base_t + i < out_size) out[base_t + i] = (float)g_topi[i];
    if (i < n_s && base_s + i < out_size) out[base_s + i] = g_sim[i];
}

// ---------------------------------------------------------------------------
// Launch
// ---------------------------------------------------------------------------
#define SG_SMEM (4 * 2 * 128 * 40 * (int)sizeof(__half))   // 81920 B
#define HG_SMEM (2 * 2 * 128 * 72 * (int)sizeof(__half))   // 73728 B

extern "C" void kernel_launch(void* const* d_in, const int* in_sizes, int n_in,
                              void* d_out, int out_size)
{
    const float* x    = (const float*)d_in[0];
    const float* fw1  = (const float*)d_in[1];
    const float* fb1  = (const float*)d_in[2];
    const float* fw2  = (const float*)d_in[3];
    const float* fb2  = (const float*)d_in[4];
    const float* kw   = (const float*)d_in[5];
    const float* kb   = (const float*)d_in[6];
    const float* keys = (const float*)d_in[7];
    const float* ew1  = (const float*)d_in[8];
    const float* eb1  = (const float*)d_in[9];
    const float* ew2  = (const float*)d_in[10];
    const float* eb2  = (const float*)d_in[11];
    const float* ew3  = (const float*)d_in[12];
    const float* eb3  = (const float*)d_in[13];
    float* out = (float*)d_out;

    cudaFuncSetAttribute(sgemm_k<0, true >, cudaFuncAttributeMaxDynamicSharedMemorySize, SG_SMEM);
    cudaFuncSetAttribute(sgemm_k<7, false>, cudaFuncAttributeMaxDynamicSharedMemorySize, SG_SMEM);
    cudaFuncSetAttribute(fused12_k,         cudaFuncAttributeMaxDynamicSharedMemorySize, SG_SMEM);
    cudaFuncSetAttribute(hgemm_k<3, true >, cudaFuncAttributeMaxDynamicSharedMemorySize, HG_SMEM);
    cudaFuncSetAttribute(hgemm_k<4, true >, cudaFuncAttributeMaxDynamicSharedMemorySize, HG_SMEM);
    cudaFuncSetAttribute(hgemm_k<5, false>, cudaFuncAttributeMaxDynamicSharedMemorySize, HG_SMEM);

    dim3 blk(256);
    dim3 tblk(32, 8);

    __half *xhi, *xlo, *fw1hi, *fw1lo, *fw2h, *fw2nhi, *fw2nlo, *kwhi, *kwlo;
    __half *wphi, *wplo, *ew1h, *ew2h, *ew3h;
    float  *zbias;
    cudaGetSymbolAddress((void**)&xhi,    g_xhi);
    cudaGetSymbolAddress((void**)&xlo,    g_xlo);
    cudaGetSymbolAddress((void**)&fw1hi,  g_fw1hi);
    cudaGetSymbolAddress((void**)&fw1lo,  g_fw1lo);
    cudaGetSymbolAddress((void**)&fw2h,   g_fw2h);
    cudaGetSymbolAddress((void**)&fw2nhi, g_fw2nhi);
    cudaGetSymbolAddress((void**)&fw2nlo, g_fw2nlo);
    cudaGetSymbolAddress((void**)&kwhi,   g_kwhi);
    cudaGetSymbolAddress((void**)&kwlo,   g_kwlo);
    cudaGetSymbolAddress((void**)&wphi,   g_wphi);
    cudaGetSymbolAddress((void**)&wplo,   g_wplo);
    cudaGetSymbolAddress((void**)&ew1h,   g_ew1h);
    cudaGetSymbolAddress((void**)&ew2h,   g_ew2h);
    cudaGetSymbolAddress((void**)&ew3h,   g_ew3h);
    cudaGetSymbolAddress((void**)&zbias,  g_zbias);

    // one-time conversions (R10-verbatim)
    natsplit_k<<<BDIM * DDIM / 4 / 256, 256>>>(x, xhi, xlo);
    natsplit_k<<<HDIM * HDIM / 4 / 256, 256>>>(fw2, fw2nhi, fw2nlo);
    wsplit_k<<<dim3(HDIM / 32, DDIM / 32), tblk>>>(fw1, fw1hi, fw1lo, DDIM, HDIM);
    wsplit_k<<<dim3(KDIM / 32, HDIM / 32), tblk>>>(kw,  kwhi,  kwlo,  HDIM, KDIM);
    wconv_k<<<dim3(HDIM / 32,        HDIM / 32,  1   ), tblk>>>(fw2, fw2h, HDIM,  HDIM);
    wconv_k<<<dim3(HDIM / 32,        HDIM / 32,  EDIM), tblk>>>(ew1, ew1h, HDIM,  HDIM);
    wconv_k<<<dim3(H2DIM / 32,       HDIM / 32,  EDIM), tblk>>>(ew2, ew2h, HDIM,  H2DIM);
    wconv_k<<<dim3((CDIM + 31) / 32, H2DIM / 32, EDIM), tblk>>>(ew3, ew3h, H2DIM, CDIM);
    bprime_k<<<KDIM, 256>>>(fb2, kw, kb);

    // W'^T = kw^T @ fw2 (fp32-grade split output)
    sgemm_k<7, false><<<dim3(HDIM / 128, 1), blk, SG_SMEM>>>(fw2nhi, fw2nlo, zbias, HDIM, HDIM);

    keysn_kernel<<<1, 256>>>(keys);
    zero_counts_kernel<<<1, 32>>>();

    // stage0: x @ fw1 -> h split (fp32-grade, relu)
    sgemm_k<0, true ><<<dim3(HDIM / 128, BDIM / 128), blk, SG_SMEM>>>(fw1hi, fw1lo, fb1, HDIM, DDIM);

    // NEW: stage1 (feats fp16) + stage2 (pk fp32) fused into one wave
    fused12_k<<<dim3(HDIM / 128 + 1, BDIM / 128), blk, SG_SMEM>>>(fb2);

    router_kernel<<<BDIM / 8, 256>>>();
    scan_kernel<<<1, 32>>>();
    scatter_kernel<<<(BDIM + 255) / 256, 256>>>();

    // expert MLPs: pure fp16 tensor-core GEMMs on grouped rows
    hgemm_k<3, true ><<<dim3(HDIM / 128,         BDIM / 128, EDIM), blk, HG_SMEM>>>(ew1h, eb1, HDIM,  HDIM);
    hgemm_k<4, true ><<<dim3(H2DIM / 128,        BDIM / 128, EDIM), blk, HG_SMEM>>>(ew2h, eb2, H2DIM, HDIM);
    hgemm_k<5, false><<<dim3((CDIM + 127) / 128, BDIM / 128, EDIM), blk, HG_SMEM>>>(ew3h, eb3, CDIM,  H2DIM);

    combine_kernel<<<BDIM, 256>>>(out);
    tail_writer_kernel<<<(BDIM * EDIM + 255) / 256, 256>>>(out, (long long)out_size);
}